// round 1
// baseline (speedup 1.0000x reference)
#include <cuda_runtime.h>

#define N_TOK 65536
#define DIM   128
#define HID   256
#define NEXP  16

// ---------------- device scratch (no allocations allowed) ----------------
__device__ int g_expert_idx[N_TOK];
__device__ int g_perm[N_TOK];
__device__ int g_counts[NEXP];
__device__ int g_offsets[NEXP + 1];
__device__ int g_cursor[NEXP];

// ---------------- init: zero histogram (graph replays re-run this) -------
__global__ void init_kernel() {
    int t = threadIdx.x;
    if (t < NEXP) g_counts[t] = 0;
}

// ---------------- gating: logits fp32, argmax (first-max tiebreak) -------
// block = 256 threads, 128 tokens/block. x tile staged in smem (padded),
// thread layout: tcol = expert lane (0..15), trow = token group (8 tokens).
__global__ __launch_bounds__(256) void gate_kernel(const float* __restrict__ x,
                                                   const float* __restrict__ Wg,
                                                   const float* __restrict__ bg) {
    extern __shared__ float sm[];
    float* xs  = sm;                    // 128 * 129
    float* wg  = xs + 128 * 129;        // 128 * 16
    float* bgs = wg + 128 * 16;         // 16
    __shared__ int hist[NEXP];

    int tid = threadIdx.x;
    if (tid < NEXP) { hist[tid] = 0; bgs[tid] = bg[tid]; }
    for (int i = tid; i < DIM * NEXP; i += 256) wg[i] = Wg[i];

    // coalesced float4 load of 128x128 x tile, scatter into padded smem
    long base = (long)blockIdx.x * 128 * DIM;
    const float4* xg = (const float4*)(x + base);
    for (int i4 = tid; i4 < 128 * DIM / 4; i4 += 256) {
        float4 v = xg[i4];
        int row = i4 >> 5;       // 32 float4 per row
        int c4  = i4 & 31;
        float* dst = xs + row * 129 + c4 * 4;
        dst[0] = v.x; dst[1] = v.y; dst[2] = v.z; dst[3] = v.w;
    }
    __syncthreads();

    int tcol = tid & 15;   // expert
    int trow = tid >> 4;   // 0..15 -> tokens trow*8 + r

    float acc[8];
#pragma unroll
    for (int r = 0; r < 8; r++) acc[r] = bgs[tcol];

    for (int k = 0; k < DIM; k++) {
        float w = wg[k * NEXP + tcol];
#pragma unroll
        for (int r = 0; r < 8; r++)
            acc[r] = fmaf(xs[(trow * 8 + r) * 129 + k], w, acc[r]);
    }

#pragma unroll
    for (int r = 0; r < 8; r++) {
        float v = acc[r];
        int   ei = tcol;
#pragma unroll
        for (int off = 8; off > 0; off >>= 1) {
            float ov = __shfl_xor_sync(0xffffffffu, v, off, 16);
            int   oe = __shfl_xor_sync(0xffffffffu, ei, off, 16);
            if (ov > v || (ov == v && oe < ei)) { v = ov; ei = oe; }
        }
        if (tcol == 0) {
            int t = blockIdx.x * 128 + trow * 8 + r;
            g_expert_idx[t] = ei;
            atomicAdd(&hist[ei], 1);
        }
    }
    __syncthreads();
    if (tid < NEXP && hist[tid]) atomicAdd(&g_counts[tid], hist[tid]);
}

// ---------------- scan: 16-entry exclusive prefix ----------------
__global__ void scan_kernel() {
    if (threadIdx.x == 0) {
        int run = 0;
        for (int e = 0; e < NEXP; e++) {
            g_offsets[e] = run;
            g_cursor[e]  = run;
            run += g_counts[e];
        }
        g_offsets[NEXP] = run;
    }
}

// ---------------- scatter: warp-aggregated bucket fill ----------------
__global__ __launch_bounds__(256) void scatter_kernel() {
    int t = blockIdx.x * 256 + threadIdx.x;
    int e = g_expert_idx[t];
    unsigned m  = __match_any_sync(0xffffffffu, e);
    int lane    = threadIdx.x & 31;
    int leader  = __ffs(m) - 1;
    int rank    = __popc(m & ((1u << lane) - 1));
    int base    = 0;
    if (lane == leader) base = atomicAdd(&g_cursor[e], __popc(m));
    base = __shfl_sync(0xffffffffu, base, leader);
    g_perm[base + rank] = t;
}

// ---------------- fused MLP: per (expert, 64-token tile) ----------------
// 256 threads as 16x16: tcol owns hidden cols {tcol+16j}, trow owns 4 tokens.
// GEMM1 64x256 (K=128) -> relu -> smem, GEMM2 64x256 (K=256) -> relu -> dot W3.
// Weights double-buffered in smem (8 rows x 256 per chunk).
__global__ __launch_bounds__(256) void mlp_kernel(
        const float* __restrict__ x,
        const float* __restrict__ W1, const float* __restrict__ b1,
        const float* __restrict__ W2, const float* __restrict__ b2,
        const float* __restrict__ W3, const float* __restrict__ b3,
        float* __restrict__ out) {
    int e = blockIdx.y;
    int beg = g_offsets[e], end = g_offsets[e + 1];
    int start = beg + blockIdx.x * 64;
    if (start >= end) return;
    int cnt = min(64, end - start);

    extern __shared__ float sm[];
    float* xs  = sm;                    // 64 * 132
    float* h1s = xs  + 64 * 132;        // 64 * 260
    float* ws0 = h1s + 64 * 260;        // 8 * 256
    float* ws1 = ws0 + 8 * 256;         // 8 * 256
    float* b1s = ws1 + 8 * 256;         // 256
    float* b2s = b1s + 256;             // 256
    float* w3s = b2s + 256;             // 256

    int tid = threadIdx.x;
    b1s[tid] = b1[e * HID + tid];
    b2s[tid] = b2[e * HID + tid];
    w3s[tid] = W3[e * HID + tid];

    // gather x tile (zero-fill past cnt)
    int lane = tid & 31, rg = tid >> 5;
    for (int r = rg; r < 64; r += 8) {
        float4 v = make_float4(0.f, 0.f, 0.f, 0.f);
        if (r < cnt) {
            int gt = g_perm[start + r];
            v = ((const float4*)(x + (long)gt * DIM))[lane];
        }
        *((float4*)(xs + r * 132) + lane) = v;   // 132*4B = 528B, 16B-aligned
    }

    const float* W1e = W1 + (long)e * DIM * HID;
    const float* W2e = W2 + (long)e * HID * HID;

    int tcol  = tid & 15;
    int trow4 = (tid >> 4) * 4;

    float acc[4][16];
#pragma unroll
    for (int r = 0; r < 4; r++)
#pragma unroll
        for (int j = 0; j < 16; j++) acc[r][j] = 0.f;

    // ---- GEMM1: h1 = relu(x @ W1 + b1), K=128 in 16 chunks of 8 ----
#pragma unroll
    for (int i = 0; i < 8; i++) ws0[i * 256 + tid] = W1e[i * 256 + tid];
    __syncthreads();
    for (int kb = 0; kb < 16; kb++) {
        float* cur = (kb & 1) ? ws1 : ws0;
        float* nxt = (kb & 1) ? ws0 : ws1;
        if (kb + 1 < 16) {
#pragma unroll
            for (int i = 0; i < 8; i++)
                nxt[i * 256 + tid] = W1e[((kb + 1) * 8 + i) * 256 + tid];
        }
#pragma unroll
        for (int kk = 0; kk < 8; kk++) {
            int k = kb * 8 + kk;
            float a[4];
#pragma unroll
            for (int r = 0; r < 4; r++) a[r] = xs[(trow4 + r) * 132 + k];
            float bv[16];
#pragma unroll
            for (int j = 0; j < 16; j++) bv[j] = cur[kk * 256 + tcol + 16 * j];
#pragma unroll
            for (int r = 0; r < 4; r++)
#pragma unroll
                for (int j = 0; j < 16; j++)
                    acc[r][j] = fmaf(a[r], bv[j], acc[r][j]);
        }
        __syncthreads();
    }

    // epilogue 1: bias + relu -> h1s
#pragma unroll
    for (int r = 0; r < 4; r++)
#pragma unroll
        for (int j = 0; j < 16; j++) {
            int c = tcol + 16 * j;
            h1s[(trow4 + r) * 260 + c] = fmaxf(acc[r][j] + b1s[c], 0.f);
            acc[r][j] = 0.f;
        }
    __syncthreads();

    // ---- GEMM2: h2 = relu(h1 @ W2 + b2), K=256 in 32 chunks of 8 ----
#pragma unroll
    for (int i = 0; i < 8; i++) ws0[i * 256 + tid] = W2e[i * 256 + tid];
    __syncthreads();
    for (int kb = 0; kb < 32; kb++) {
        float* cur = (kb & 1) ? ws1 : ws0;
        float* nxt = (kb & 1) ? ws0 : ws1;
        if (kb + 1 < 32) {
#pragma unroll
            for (int i = 0; i < 8; i++)
                nxt[i * 256 + tid] = W2e[((kb + 1) * 8 + i) * 256 + tid];
        }
#pragma unroll
        for (int kk = 0; kk < 8; kk++) {
            int k = kb * 8 + kk;
            float a[4];
#pragma unroll
            for (int r = 0; r < 4; r++) a[r] = h1s[(trow4 + r) * 260 + k];
            float bv[16];
#pragma unroll
            for (int j = 0; j < 16; j++) bv[j] = cur[kk * 256 + tcol + 16 * j];
#pragma unroll
            for (int r = 0; r < 4; r++)
#pragma unroll
                for (int j = 0; j < 16; j++)
                    acc[r][j] = fmaf(a[r], bv[j], acc[r][j]);
        }
        __syncthreads();
    }

    // ---- epilogue 2: relu + dot W3 + b3, 16-lane reduce, scatter out ----
    float b3v = b3[e];
#pragma unroll
    for (int r = 0; r < 4; r++) {
        float p = 0.f;
#pragma unroll
        for (int j = 0; j < 16; j++) {
            int c = tcol + 16 * j;
            p = fmaf(fmaxf(acc[r][j] + b2s[c], 0.f), w3s[c], p);
        }
#pragma unroll
        for (int off = 8; off > 0; off >>= 1)
            p += __shfl_down_sync(0xffffffffu, p, off, 16);
        if (tcol == 0) {
            int t = trow4 + r;
            if (t < cnt) out[g_perm[start + t]] = p + b3v;
        }
    }
}

// ---------------- launch ----------------
extern "C" void kernel_launch(void* const* d_in, const int* in_sizes, int n_in,
                              void* d_out, int out_size) {
    const float* x  = (const float*)d_in[0];
    const float* Wg = (const float*)d_in[1];
    const float* bg = (const float*)d_in[2];
    const float* W1 = (const float*)d_in[3];
    const float* b1 = (const float*)d_in[4];
    const float* W2 = (const float*)d_in[5];
    const float* b2 = (const float*)d_in[6];
    const float* W3 = (const float*)d_in[7];
    const float* b3 = (const float*)d_in[8];
    float* out = (float*)d_out;

    size_t gate_smem = (size_t)(128 * 129 + 128 * 16 + 16) * sizeof(float);
    size_t mlp_smem  = (size_t)(64 * 132 + 64 * 260 + 2 * 8 * 256 + 3 * 256) * sizeof(float);
    cudaFuncSetAttribute(gate_kernel, cudaFuncAttributeMaxDynamicSharedMemorySize, (int)gate_smem);
    cudaFuncSetAttribute(mlp_kernel,  cudaFuncAttributeMaxDynamicSharedMemorySize, (int)mlp_smem);

    init_kernel<<<1, 32>>>();
    gate_kernel<<<N_TOK / 128, 256, gate_smem>>>(x, Wg, bg);
    scan_kernel<<<1, 32>>>();
    scatter_kernel<<<N_TOK / 256, 256>>>();
    mlp_kernel<<<dim3(1024, NEXP), 256, mlp_smem>>>(x, W1, b1, W2, b2, W3, b3, out);
}

// round 3
// speedup vs baseline: 3.2453x; 3.2453x over previous
#include <cuda_runtime.h>
#include <cstdint>

#define N_TOK 65536
#define DIM   128
#define HID   256
#define NEXP  16

// ---------------- device scratch ----------------
__device__ int g_expert_idx[N_TOK];
__device__ int g_perm[N_TOK];
__device__ int g_counts[NEXP];
__device__ int g_offsets[NEXP + 1];
__device__ int g_cursor[NEXP];

// ---------------- helpers ----------------
__device__ __forceinline__ uint32_t smem_u32(const void* p) {
    uint32_t a;
    asm("{ .reg .u64 t; cvta.to.shared.u64 t, %1; cvt.u32.u64 %0, t; }" : "=r"(a) : "l"(p));
    return a;
}
__device__ __forceinline__ float tf32_round(float f) {
    uint32_t o;
    asm("cvt.rna.tf32.f32 %0, %1;" : "=r"(o) : "f"(f));
    return __uint_as_float(o);
}
__device__ __forceinline__ uint32_t tf32_bits(float f) {
    uint32_t o;
    asm("cvt.rna.tf32.f32 %0, %1;" : "=r"(o) : "f"(f));
    return o;
}

#define MMA_TF32(acc, a, b) \
    asm volatile("mma.sync.aligned.m16n8k8.row.col.f32.tf32.tf32.f32 " \
        "{%0,%1,%2,%3}, {%4,%5,%6,%7}, {%8,%9}, {%0,%1,%2,%3};" \
        : "+f"((acc)[0]), "+f"((acc)[1]), "+f"((acc)[2]), "+f"((acc)[3]) \
        : "r"((a)[0]), "r"((a)[1]), "r"((a)[2]), "r"((a)[3]), \
          "r"((b)[0]), "r"((b)[1]))

#define CP_ASYNC16(dst, src) \
    asm volatile("cp.async.cg.shared.global [%0], [%1], 16;" :: "r"(dst), "l"(src))
#define CP_COMMIT() asm volatile("cp.async.commit_group;" ::: "memory")
#define CP_WAIT0()  asm volatile("cp.async.wait_group 0;"  ::: "memory")

// ---------------- init / gate / scan / scatter (unchanged, fp32-exact) ----------------
__global__ void init_kernel() {
    int t = threadIdx.x;
    if (t < NEXP) g_counts[t] = 0;
}

__global__ __launch_bounds__(256) void gate_kernel(const float* __restrict__ x,
                                                   const float* __restrict__ Wg,
                                                   const float* __restrict__ bg) {
    extern __shared__ float sm[];
    float* xs  = sm;
    float* wg  = xs + 128 * 129;
    float* bgs = wg + 128 * 16;
    __shared__ int hist[NEXP];

    int tid = threadIdx.x;
    if (tid < NEXP) { hist[tid] = 0; bgs[tid] = bg[tid]; }
    for (int i = tid; i < DIM * NEXP; i += 256) wg[i] = Wg[i];

    long base = (long)blockIdx.x * 128 * DIM;
    const float4* xg = (const float4*)(x + base);
    for (int i4 = tid; i4 < 128 * DIM / 4; i4 += 256) {
        float4 v = xg[i4];
        int row = i4 >> 5;
        int c4  = i4 & 31;
        float* dst = xs + row * 129 + c4 * 4;
        dst[0] = v.x; dst[1] = v.y; dst[2] = v.z; dst[3] = v.w;
    }
    __syncthreads();

    int tcol = tid & 15;
    int trow = tid >> 4;

    float acc[8];
#pragma unroll
    for (int r = 0; r < 8; r++) acc[r] = bgs[tcol];
    for (int k = 0; k < DIM; k++) {
        float w = wg[k * NEXP + tcol];
#pragma unroll
        for (int r = 0; r < 8; r++)
            acc[r] = fmaf(xs[(trow * 8 + r) * 129 + k], w, acc[r]);
    }
#pragma unroll
    for (int r = 0; r < 8; r++) {
        float v = acc[r];
        int ei = tcol;
#pragma unroll
        for (int off = 8; off > 0; off >>= 1) {
            float ov = __shfl_xor_sync(0xffffffffu, v, off, 16);
            int   oe = __shfl_xor_sync(0xffffffffu, ei, off, 16);
            if (ov > v || (ov == v && oe < ei)) { v = ov; ei = oe; }
        }
        if (tcol == 0) {
            int t = blockIdx.x * 128 + trow * 8 + r;
            g_expert_idx[t] = ei;
            atomicAdd(&hist[ei], 1);
        }
    }
    __syncthreads();
    if (tid < NEXP && hist[tid]) atomicAdd(&g_counts[tid], hist[tid]);
}

__global__ void scan_kernel() {
    if (threadIdx.x == 0) {
        int run = 0;
        for (int e = 0; e < NEXP; e++) {
            g_offsets[e] = run;
            g_cursor[e]  = run;
            run += g_counts[e];
        }
        g_offsets[NEXP] = run;
    }
}

__global__ __launch_bounds__(256) void scatter_kernel() {
    int t = blockIdx.x * 256 + threadIdx.x;
    int e = g_expert_idx[t];
    unsigned m  = __match_any_sync(0xffffffffu, e);
    int lane    = threadIdx.x & 31;
    int leader  = __ffs(m) - 1;
    int rank    = __popc(m & ((1u << lane) - 1));
    int base    = 0;
    if (lane == leader) base = atomicAdd(&g_cursor[e], __popc(m));
    base = __shfl_sync(0xffffffffu, base, leader);
    g_perm[base + rank] = t;
}

// ---------------- tf32 mma.sync grouped MLP ----------------
// smem layout (floats):
//   ws0  [16][264]   k-chunk of W, buffer 0
//   ws1  [16][264]   buffer 1
//   b1s[256] b2s[256] w3s[256] ps[256]
//   union region: xs [128][132] (GEMM1 A)  /  h1 [128][268] (GEMM2 A)
#define WS_PAD 264
#define XS_PAD 132
#define H1_PAD 268
#define F_WS0   0
#define F_WS1   (16 * WS_PAD)
#define F_B1S   (2 * 16 * WS_PAD)
#define F_B2S   (F_B1S + 256)
#define F_W3S   (F_B2S + 256)
#define F_PS    (F_W3S + 256)
#define F_UNION (F_PS + 256)
#define MLP_SMEM ((F_UNION + 128 * H1_PAD) * 4)

// stage one 16-row k-chunk of W ([k][256] layout, row stride 256) into ws
__device__ __forceinline__ void cp_chunk(const float* __restrict__ W, int kc,
                                         uint32_t ws_smem, int tid) {
#pragma unroll
    for (int i = 0; i < 4; i++) {
        int f4  = tid + 256 * i;       // 1024 float4s total
        int row = f4 >> 6;             // 0..15
        int c4  = f4 & 63;             // float4 within 256-float row
        const float* src = W + (long)(kc * 16 + row) * HID + c4 * 4;
        uint32_t dst = ws_smem + (uint32_t)(row * WS_PAD + c4 * 4) * 4u;
        CP_ASYNC16(dst, src);
    }
}

__global__ __launch_bounds__(256, 1) void mlp_tc_kernel(
        const float* __restrict__ x,
        const float* __restrict__ W1, const float* __restrict__ b1,
        const float* __restrict__ W2, const float* __restrict__ b2,
        const float* __restrict__ W3, const float* __restrict__ b3,
        float* __restrict__ out) {
    int e   = blockIdx.y;
    int beg = g_offsets[e], end = g_offsets[e + 1];
    int start = beg + blockIdx.x * 128;
    if (start >= end) return;
    int cnt = min(128, end - start);

    extern __shared__ float sm[];
    float* b1s = sm + F_B1S;
    float* b2s = sm + F_B2S;
    float* w3s = sm + F_W3S;
    float* ps  = sm + F_PS;
    float* xs  = sm + F_UNION;          // GEMM1 A
    float* h1  = sm + F_UNION;          // GEMM2 A (aliases xs)
    uint32_t ws_addr[2] = { smem_u32(sm + F_WS0), smem_u32(sm + F_WS1) };
    float*   ws_ptr[2]  = { sm + F_WS0, sm + F_WS1 };

    int tid = threadIdx.x;
    int wid = tid >> 5, lid = tid & 31;
    int g = lid >> 2, t = lid & 3;      // groupID / thread-in-group
    int wm = wid & 3;                   // M warp (rows wm*32..+31)
    int wn = wid >> 2;                  // N warp (cols wn*128..+127)

    b1s[tid] = b1[e * HID + tid];
    b2s[tid] = b2[e * HID + tid];
    w3s[tid] = W3[e * HID + tid];

    // gather A1 = x[perm] tile, tf32-rounded, into xs [128][132]
#pragma unroll
    for (int i = 0; i < 16; i++) {
        int f   = tid + 256 * i;        // 4096 float4s
        int row = f >> 5;
        int c4  = f & 31;
        float4 v = make_float4(0.f, 0.f, 0.f, 0.f);
        if (row < cnt) {
            int gt = g_perm[start + row];
            v = *(const float4*)(x + (long)gt * DIM + c4 * 4);
        }
        v.x = tf32_round(v.x); v.y = tf32_round(v.y);
        v.z = tf32_round(v.z); v.w = tf32_round(v.w);
        *(float4*)(xs + row * XS_PAD + c4 * 4) = v;
    }

    const float* W1e = W1 + (long)e * DIM * HID;
    const float* W2e = W2 + (long)e * HID * HID;

    float acc[2][16][4];
#pragma unroll
    for (int fm = 0; fm < 2; fm++)
#pragma unroll
        for (int fn = 0; fn < 16; fn++)
#pragma unroll
            for (int q = 0; q < 4; q++) acc[fm][fn][q] = 0.f;

    // ================= GEMM1: K = 128, 8 chunks of 16 =================
    cp_chunk(W1e, 0, ws_addr[0], tid);
    CP_COMMIT();
    __syncthreads();                    // xs ready (cp not yet)

#pragma unroll 1
    for (int ch = 0; ch < 8; ch++) {
        CP_WAIT0();
        __syncthreads();
        if (ch < 7) { cp_chunk(W1e, ch + 1, ws_addr[(ch + 1) & 1], tid); CP_COMMIT(); }
        const float* wsb = ws_ptr[ch & 1];
#pragma unroll
        for (int kk = 0; kk < 2; kk++) {
            uint32_t a[2][4];
#pragma unroll
            for (int fm = 0; fm < 2; fm++) {
                const float* xr = xs + (wm * 32 + fm * 16 + g) * XS_PAD + ch * 16 + kk * 8 + t;
                a[fm][0] = __float_as_uint(xr[0]);
                a[fm][1] = __float_as_uint(xr[8 * XS_PAD]);
                a[fm][2] = __float_as_uint(xr[4]);
                a[fm][3] = __float_as_uint(xr[8 * XS_PAD + 4]);
            }
            uint32_t b[16][2];
            const float* wr = wsb + (kk * 8 + t) * WS_PAD + wn * 128 + g;
#pragma unroll
            for (int fn = 0; fn < 16; fn++) {
                b[fn][0] = tf32_bits(wr[fn * 8]);
                b[fn][1] = tf32_bits(wr[4 * WS_PAD + fn * 8]);
            }
#pragma unroll
            for (int fm = 0; fm < 2; fm++)
#pragma unroll
                for (int fn = 0; fn < 16; fn++)
                    MMA_TF32(acc[fm][fn], a[fm], b[fn]);
        }
    }

    __syncthreads();                    // all warps done reading xs

    // ---- epilogue 1: h1 = tf32(relu(acc + b1)) into [128][268] ----
#pragma unroll
    for (int fm = 0; fm < 2; fm++) {
        int r = wm * 32 + fm * 16 + g;
#pragma unroll
        for (int fn = 0; fn < 16; fn++) {
            int c = wn * 128 + fn * 8 + t * 2;
            float2 v0, v1;
            v0.x = tf32_round(fmaxf(acc[fm][fn][0] + b1s[c],     0.f));
            v0.y = tf32_round(fmaxf(acc[fm][fn][1] + b1s[c + 1], 0.f));
            v1.x = tf32_round(fmaxf(acc[fm][fn][2] + b1s[c],     0.f));
            v1.y = tf32_round(fmaxf(acc[fm][fn][3] + b1s[c + 1], 0.f));
            *(float2*)(h1 + r * H1_PAD + c)       = v0;
            *(float2*)(h1 + (r + 8) * H1_PAD + c) = v1;
            acc[fm][fn][0] = 0.f; acc[fm][fn][1] = 0.f;
            acc[fm][fn][2] = 0.f; acc[fm][fn][3] = 0.f;
        }
    }
    __syncthreads();

    // ================= GEMM2: K = 256, 16 chunks of 16 =================
    cp_chunk(W2e, 0, ws_addr[0], tid);
    CP_COMMIT();

#pragma unroll 1
    for (int ch = 0; ch < 16; ch++) {
        CP_WAIT0();
        __syncthreads();
        if (ch < 15) { cp_chunk(W2e, ch + 1, ws_addr[(ch + 1) & 1], tid); CP_COMMIT(); }
        const float* wsb = ws_ptr[ch & 1];
#pragma unroll
        for (int kk = 0; kk < 2; kk++) {
            uint32_t a[2][4];
#pragma unroll
            for (int fm = 0; fm < 2; fm++) {
                const float* hr = h1 + (wm * 32 + fm * 16 + g) * H1_PAD + ch * 16 + kk * 8 + t;
                a[fm][0] = __float_as_uint(hr[0]);
                a[fm][1] = __float_as_uint(hr[8 * H1_PAD]);
                a[fm][2] = __float_as_uint(hr[4]);
                a[fm][3] = __float_as_uint(hr[8 * H1_PAD + 4]);
            }
            uint32_t b[16][2];
            const float* wr = wsb + (kk * 8 + t) * WS_PAD + wn * 128 + g;
#pragma unroll
            for (int fn = 0; fn < 16; fn++) {
                b[fn][0] = tf32_bits(wr[fn * 8]);
                b[fn][1] = tf32_bits(wr[4 * WS_PAD + fn * 8]);
            }
#pragma unroll
            for (int fm = 0; fm < 2; fm++)
#pragma unroll
                for (int fn = 0; fn < 16; fn++)
                    MMA_TF32(acc[fm][fn], a[fm], b[fn]);
        }
    }

    // ---- epilogue 2: y = relu(acc + b2) . w3 + b3 ----
    float part[2][2];
    part[0][0] = part[0][1] = part[1][0] = part[1][1] = 0.f;
#pragma unroll
    for (int fm = 0; fm < 2; fm++)
#pragma unroll
        for (int fn = 0; fn < 16; fn++) {
            int c = wn * 128 + fn * 8 + t * 2;
            part[fm][0] = fmaf(fmaxf(acc[fm][fn][0] + b2s[c],     0.f), w3s[c],     part[fm][0]);
            part[fm][0] = fmaf(fmaxf(acc[fm][fn][1] + b2s[c + 1], 0.f), w3s[c + 1], part[fm][0]);
            part[fm][1] = fmaf(fmaxf(acc[fm][fn][2] + b2s[c],     0.f), w3s[c],     part[fm][1]);
            part[fm][1] = fmaf(fmaxf(acc[fm][fn][3] + b2s[c + 1], 0.f), w3s[c + 1], part[fm][1]);
        }
#pragma unroll
    for (int fm = 0; fm < 2; fm++)
#pragma unroll
        for (int h = 0; h < 2; h++) {
            part[fm][h] += __shfl_xor_sync(0xffffffffu, part[fm][h], 1);
            part[fm][h] += __shfl_xor_sync(0xffffffffu, part[fm][h], 2);
        }
    if (t == 0) {
#pragma unroll
        for (int fm = 0; fm < 2; fm++) {
            int r = wm * 32 + fm * 16 + g;
            ps[r * 2 + wn]       = part[fm][0];
            ps[(r + 8) * 2 + wn] = part[fm][1];
        }
    }
    __syncthreads();

    if (tid < cnt)
        out[g_perm[start + tid]] = ps[tid * 2] + ps[tid * 2 + 1] + b3[e];
}

// ---------------- launch ----------------
extern "C" void kernel_launch(void* const* d_in, const int* in_sizes, int n_in,
                              void* d_out, int out_size) {
    const float* x  = (const float*)d_in[0];
    const float* Wg = (const float*)d_in[1];
    const float* bg = (const float*)d_in[2];
    const float* W1 = (const float*)d_in[3];
    const float* b1 = (const float*)d_in[4];
    const float* W2 = (const float*)d_in[5];
    const float* b2 = (const float*)d_in[6];
    const float* W3 = (const float*)d_in[7];
    const float* b3 = (const float*)d_in[8];
    float* out = (float*)d_out;

    size_t gate_smem = (size_t)(128 * 129 + 128 * 16 + 16) * sizeof(float);
    cudaFuncSetAttribute(gate_kernel, cudaFuncAttributeMaxDynamicSharedMemorySize, (int)gate_smem);
    cudaFuncSetAttribute(mlp_tc_kernel, cudaFuncAttributeMaxDynamicSharedMemorySize, MLP_SMEM);

    init_kernel<<<1, 32>>>();
    gate_kernel<<<N_TOK / 128, 256, gate_smem>>>(x, Wg, bg);
    scan_kernel<<<1, 32>>>();
    scatter_kernel<<<N_TOK / 256, 256>>>();
    mlp_tc_kernel<<<dim3(512, NEXP), 256, MLP_SMEM>>>(x, W1, b1, W2, b2, W3, b3, out);
    (void)n_in; (void)in_sizes; (void)out_size;
}

// round 4
// speedup vs baseline: 3.5375x; 1.0900x over previous
#include <cuda_runtime.h>
#include <cstdint>

#define N_TOK 65536
#define DIM   128
#define HID   256
#define NEXP  16

// ---------------- device scratch ----------------
__device__ int g_expert_idx[N_TOK];
__device__ int g_perm[N_TOK];
__device__ int g_counts[NEXP];
__device__ int g_offsets[NEXP + 1];
__device__ int g_cursor[NEXP];
__device__ float g_W1r[NEXP * DIM * HID];   // tf32-rounded W1, same [e][k][n] layout
__device__ float g_W2r[NEXP * HID * HID];   // tf32-rounded W2

// ---------------- helpers ----------------
__device__ __forceinline__ float tf32_round(float f) {
    uint32_t o;
    asm("cvt.rna.tf32.f32 %0, %1;" : "=r"(o) : "f"(f));
    return __uint_as_float(o);
}

#define MMA_TF32(acc, a, b) \
    asm volatile("mma.sync.aligned.m16n8k8.row.col.f32.tf32.tf32.f32 " \
        "{%0,%1,%2,%3}, {%4,%5,%6,%7}, {%8,%9}, {%0,%1,%2,%3};" \
        : "+f"((acc)[0]), "+f"((acc)[1]), "+f"((acc)[2]), "+f"((acc)[3]) \
        : "r"((a)[0]), "r"((a)[1]), "r"((a)[2]), "r"((a)[3]), \
          "r"((b)[0]), "r"((b)[1]))

#define CP_ASYNC16(dst, src) \
    asm volatile("cp.async.cg.shared.global [%0], [%1], 16;" :: "r"(dst), "l"(src))
#define CP_COMMIT() asm volatile("cp.async.commit_group;" ::: "memory")
#define CP_WAIT0()  asm volatile("cp.async.wait_group 0;"  ::: "memory")

__device__ __forceinline__ uint32_t smem_u32(const void* p) {
    uint32_t a;
    asm("{ .reg .u64 t; cvta.to.shared.u64 t, %1; cvt.u32.u64 %0, t; }" : "=r"(a) : "l"(p));
    return a;
}

// ---------------- init / gate / scan / scatter (fp32-exact routing) ----------------
__global__ void init_kernel() {
    int t = threadIdx.x;
    if (t < NEXP) g_counts[t] = 0;
}

__global__ __launch_bounds__(256) void gate_kernel(const float* __restrict__ x,
                                                   const float* __restrict__ Wg,
                                                   const float* __restrict__ bg) {
    extern __shared__ float sm[];
    float* xs  = sm;
    float* wg  = xs + 128 * 129;
    float* bgs = wg + 128 * 16;
    __shared__ int hist[NEXP];

    int tid = threadIdx.x;
    if (tid < NEXP) { hist[tid] = 0; bgs[tid] = bg[tid]; }
    for (int i = tid; i < DIM * NEXP; i += 256) wg[i] = Wg[i];

    long base = (long)blockIdx.x * 128 * DIM;
    const float4* xg = (const float4*)(x + base);
    for (int i4 = tid; i4 < 128 * DIM / 4; i4 += 256) {
        float4 v = xg[i4];
        int row = i4 >> 5;
        int c4  = i4 & 31;
        float* dst = xs + row * 129 + c4 * 4;
        dst[0] = v.x; dst[1] = v.y; dst[2] = v.z; dst[3] = v.w;
    }
    __syncthreads();

    int tcol = tid & 15;
    int trow = tid >> 4;

    float acc[8];
#pragma unroll
    for (int r = 0; r < 8; r++) acc[r] = bgs[tcol];
    for (int k = 0; k < DIM; k++) {
        float w = wg[k * NEXP + tcol];
#pragma unroll
        for (int r = 0; r < 8; r++)
            acc[r] = fmaf(xs[(trow * 8 + r) * 129 + k], w, acc[r]);
    }
#pragma unroll
    for (int r = 0; r < 8; r++) {
        float v = acc[r];
        int ei = tcol;
#pragma unroll
        for (int off = 8; off > 0; off >>= 1) {
            float ov = __shfl_xor_sync(0xffffffffu, v, off, 16);
            int   oe = __shfl_xor_sync(0xffffffffu, ei, off, 16);
            if (ov > v || (ov == v && oe < ei)) { v = ov; ei = oe; }
        }
        if (tcol == 0) {
            int t = blockIdx.x * 128 + trow * 8 + r;
            g_expert_idx[t] = ei;
            atomicAdd(&hist[ei], 1);
        }
    }
    __syncthreads();
    if (tid < NEXP && hist[tid]) atomicAdd(&g_counts[tid], hist[tid]);
}

__global__ void scan_kernel() {
    if (threadIdx.x == 0) {
        int run = 0;
        for (int e = 0; e < NEXP; e++) {
            g_offsets[e] = run;
            g_cursor[e]  = run;
            run += g_counts[e];
        }
        g_offsets[NEXP] = run;
    }
}

__global__ __launch_bounds__(256) void scatter_kernel() {
    int t = blockIdx.x * 256 + threadIdx.x;
    int e = g_expert_idx[t];
    unsigned m  = __match_any_sync(0xffffffffu, e);
    int lane    = threadIdx.x & 31;
    int leader  = __ffs(m) - 1;
    int rank    = __popc(m & ((1u << lane) - 1));
    int base    = 0;
    if (lane == leader) base = atomicAdd(&g_cursor[e], __popc(m));
    base = __shfl_sync(0xffffffffu, base, leader);
    g_perm[base + rank] = t;
}

// ---------------- pre-round weights to tf32 (hoists cvt out of mainloop) ----------------
__global__ __launch_bounds__(256) void round_kernel(const float4* __restrict__ W1,
                                                    const float4* __restrict__ W2) {
    int i = blockIdx.x * 256 + threadIdx.x;          // 0 .. NEXP*HID*HID/4 - 1
    float4 v = W2[i];
    v.x = tf32_round(v.x); v.y = tf32_round(v.y);
    v.z = tf32_round(v.z); v.w = tf32_round(v.w);
    ((float4*)g_W2r)[i] = v;
    if (i < NEXP * DIM * HID / 4) {
        float4 u = W1[i];
        u.x = tf32_round(u.x); u.y = tf32_round(u.y);
        u.z = tf32_round(u.z); u.w = tf32_round(u.w);
        ((float4*)g_W1r)[i] = u;
    }
}

// ---------------- tf32 mma.sync grouped MLP ----------------
// 8 warps as 2(M) x 4(N); warp tile 64x64 (fm=4, fn=8).
#define WS_PAD 264
#define XS_PAD 132
#define H1_PAD 268
#define F_WS0   0
#define F_WS1   (16 * WS_PAD)
#define F_B1S   (2 * 16 * WS_PAD)
#define F_B2S   (F_B1S + 256)
#define F_W3S   (F_B2S + 256)
#define F_PS    (F_W3S + 256)
#define F_UNION (F_PS + 512)
#define MLP_SMEM ((F_UNION + 128 * H1_PAD) * 4)

__device__ __forceinline__ void cp_chunk(const float* __restrict__ W, int kc,
                                         uint32_t ws_smem, int tid) {
#pragma unroll
    for (int i = 0; i < 4; i++) {
        int f4  = tid + 256 * i;       // 1024 float4s = 16 rows x 256 floats
        int row = f4 >> 6;
        int c4  = f4 & 63;
        const float* src = W + (long)(kc * 16 + row) * HID + c4 * 4;
        uint32_t dst = ws_smem + (uint32_t)(row * WS_PAD + c4 * 4) * 4u;
        CP_ASYNC16(dst, src);
    }
}

__global__ __launch_bounds__(256, 1) void mlp_tc_kernel(
        const float* __restrict__ x,
        const float* __restrict__ b1, const float* __restrict__ b2,
        const float* __restrict__ W3, const float* __restrict__ b3,
        float* __restrict__ out) {
    int e   = blockIdx.y;
    int beg = g_offsets[e], end = g_offsets[e + 1];
    int start = beg + blockIdx.x * 128;
    if (start >= end) return;
    int cnt = min(128, end - start);

    extern __shared__ float sm[];
    float* b1s = sm + F_B1S;
    float* b2s = sm + F_B2S;
    float* w3s = sm + F_W3S;
    float* ps  = sm + F_PS;
    float* xs  = sm + F_UNION;          // GEMM1 A
    float* h1  = sm + F_UNION;          // GEMM2 A (aliases xs)
    uint32_t ws_addr[2] = { smem_u32(sm + F_WS0), smem_u32(sm + F_WS1) };
    float*   ws_ptr[2]  = { sm + F_WS0, sm + F_WS1 };

    int tid = threadIdx.x;
    int wid = tid >> 5, lid = tid & 31;
    int g = lid >> 2, t = lid & 3;
    int wm = wid & 1;                   // M warp: rows wm*64 .. +63
    int wn = wid >> 1;                  // N warp: cols wn*64 .. +63

    b1s[tid] = b1[e * HID + tid];
    b2s[tid] = b2[e * HID + tid];
    w3s[tid] = W3[e * HID + tid];

    // gather A1 = x[perm], tf32-rounded, into xs [128][132]
#pragma unroll
    for (int i = 0; i < 16; i++) {
        int f   = tid + 256 * i;
        int row = f >> 5;
        int c4  = f & 31;
        float4 v = make_float4(0.f, 0.f, 0.f, 0.f);
        if (row < cnt) {
            int gt = g_perm[start + row];
            v = *(const float4*)(x + (long)gt * DIM + c4 * 4);
        }
        v.x = tf32_round(v.x); v.y = tf32_round(v.y);
        v.z = tf32_round(v.z); v.w = tf32_round(v.w);
        *(float4*)(xs + row * XS_PAD + c4 * 4) = v;
    }

    const float* W1e = g_W1r + (long)e * DIM * HID;
    const float* W2e = g_W2r + (long)e * HID * HID;

    float acc[4][8][4];
#pragma unroll
    for (int fm = 0; fm < 4; fm++)
#pragma unroll
        for (int fn = 0; fn < 8; fn++)
#pragma unroll
            for (int q = 0; q < 4; q++) acc[fm][fn][q] = 0.f;

    // ================= GEMM1: K = 128, 8 chunks of 16 =================
    cp_chunk(W1e, 0, ws_addr[0], tid);
    CP_COMMIT();
    __syncthreads();

#pragma unroll 1
    for (int ch = 0; ch < 8; ch++) {
        CP_WAIT0();
        __syncthreads();
        if (ch < 7) { cp_chunk(W1e, ch + 1, ws_addr[(ch + 1) & 1], tid); CP_COMMIT(); }
        const float* wsb = ws_ptr[ch & 1];
#pragma unroll
        for (int kk = 0; kk < 2; kk++) {
            uint32_t a[4][4];
#pragma unroll
            for (int fm = 0; fm < 4; fm++) {
                const float* xr = xs + (wm * 64 + fm * 16 + g) * XS_PAD + ch * 16 + kk * 8 + t;
                a[fm][0] = __float_as_uint(xr[0]);
                a[fm][1] = __float_as_uint(xr[8 * XS_PAD]);
                a[fm][2] = __float_as_uint(xr[4]);
                a[fm][3] = __float_as_uint(xr[8 * XS_PAD + 4]);
            }
            uint32_t b[8][2];
            const float* wr = wsb + (kk * 8 + t) * WS_PAD + wn * 64 + g;
#pragma unroll
            for (int fn = 0; fn < 8; fn++) {
                b[fn][0] = __float_as_uint(wr[fn * 8]);
                b[fn][1] = __float_as_uint(wr[4 * WS_PAD + fn * 8]);
            }
#pragma unroll
            for (int fm = 0; fm < 4; fm++)
#pragma unroll
                for (int fn = 0; fn < 8; fn++)
                    MMA_TF32(acc[fm][fn], a[fm], b[fn]);
        }
    }

    __syncthreads();                    // all warps done reading xs

    // ---- epilogue 1: h1 = tf32(relu(acc + b1)) into [128][268] ----
#pragma unroll
    for (int fm = 0; fm < 4; fm++) {
        int r = wm * 64 + fm * 16 + g;
#pragma unroll
        for (int fn = 0; fn < 8; fn++) {
            int c = wn * 64 + fn * 8 + t * 2;
            float2 v0, v1;
            v0.x = tf32_round(fmaxf(acc[fm][fn][0] + b1s[c],     0.f));
            v0.y = tf32_round(fmaxf(acc[fm][fn][1] + b1s[c + 1], 0.f));
            v1.x = tf32_round(fmaxf(acc[fm][fn][2] + b1s[c],     0.f));
            v1.y = tf32_round(fmaxf(acc[fm][fn][3] + b1s[c + 1], 0.f));
            *(float2*)(h1 + r * H1_PAD + c)       = v0;
            *(float2*)(h1 + (r + 8) * H1_PAD + c) = v1;
            acc[fm][fn][0] = 0.f; acc[fm][fn][1] = 0.f;
            acc[fm][fn][2] = 0.f; acc[fm][fn][3] = 0.f;
        }
    }
    __syncthreads();

    // ================= GEMM2: K = 256, 16 chunks of 16 =================
    cp_chunk(W2e, 0, ws_addr[0], tid);
    CP_COMMIT();

#pragma unroll 1
    for (int ch = 0; ch < 16; ch++) {
        CP_WAIT0();
        __syncthreads();
        if (ch < 15) { cp_chunk(W2e, ch + 1, ws_addr[(ch + 1) & 1], tid); CP_COMMIT(); }
        const float* wsb = ws_ptr[ch & 1];
#pragma unroll
        for (int kk = 0; kk < 2; kk++) {
            uint32_t a[4][4];
#pragma unroll
            for (int fm = 0; fm < 4; fm++) {
                const float* hr = h1 + (wm * 64 + fm * 16 + g) * H1_PAD + ch * 16 + kk * 8 + t;
                a[fm][0] = __float_as_uint(hr[0]);
                a[fm][1] = __float_as_uint(hr[8 * H1_PAD]);
                a[fm][2] = __float_as_uint(hr[4]);
                a[fm][3] = __float_as_uint(hr[8 * H1_PAD + 4]);
            }
            uint32_t b[8][2];
            const float* wr = wsb + (kk * 8 + t) * WS_PAD + wn * 64 + g;
#pragma unroll
            for (int fn = 0; fn < 8; fn++) {
                b[fn][0] = __float_as_uint(wr[fn * 8]);
                b[fn][1] = __float_as_uint(wr[4 * WS_PAD + fn * 8]);
            }
#pragma unroll
            for (int fm = 0; fm < 4; fm++)
#pragma unroll
                for (int fn = 0; fn < 8; fn++)
                    MMA_TF32(acc[fm][fn], a[fm], b[fn]);
        }
    }

    // ---- epilogue 2: y = relu(acc + b2) . w3 + b3 ----
    float part[4][2];
#pragma unroll
    for (int fm = 0; fm < 4; fm++) { part[fm][0] = 0.f; part[fm][1] = 0.f; }
#pragma unroll
    for (int fm = 0; fm < 4; fm++)
#pragma unroll
        for (int fn = 0; fn < 8; fn++) {
            int c = wn * 64 + fn * 8 + t * 2;
            part[fm][0] = fmaf(fmaxf(acc[fm][fn][0] + b2s[c],     0.f), w3s[c],     part[fm][0]);
            part[fm][0] = fmaf(fmaxf(acc[fm][fn][1] + b2s[c + 1], 0.f), w3s[c + 1], part[fm][0]);
            part[fm][1] = fmaf(fmaxf(acc[fm][fn][2] + b2s[c],     0.f), w3s[c],     part[fm][1]);
            part[fm][1] = fmaf(fmaxf(acc[fm][fn][3] + b2s[c + 1], 0.f), w3s[c + 1], part[fm][1]);
        }
#pragma unroll
    for (int fm = 0; fm < 4; fm++)
#pragma unroll
        for (int h = 0; h < 2; h++) {
            part[fm][h] += __shfl_xor_sync(0xffffffffu, part[fm][h], 1);
            part[fm][h] += __shfl_xor_sync(0xffffffffu, part[fm][h], 2);
        }
    if (t == 0) {
#pragma unroll
        for (int fm = 0; fm < 4; fm++) {
            int r = wm * 64 + fm * 16 + g;
            ps[r * 4 + wn]       = part[fm][0];
            ps[(r + 8) * 4 + wn] = part[fm][1];
        }
    }
    __syncthreads();

    if (tid < cnt)
        out[g_perm[start + tid]] = ps[tid * 4] + ps[tid * 4 + 1]
                                 + ps[tid * 4 + 2] + ps[tid * 4 + 3] + b3[e];
}

// ---------------- launch ----------------
extern "C" void kernel_launch(void* const* d_in, const int* in_sizes, int n_in,
                              void* d_out, int out_size) {
    const float* x  = (const float*)d_in[0];
    const float* Wg = (const float*)d_in[1];
    const float* bg = (const float*)d_in[2];
    const float* W1 = (const float*)d_in[3];
    const float* b1 = (const float*)d_in[4];
    const float* W2 = (const float*)d_in[5];
    const float* b2 = (const float*)d_in[6];
    const float* W3 = (const float*)d_in[7];
    const float* b3 = (const float*)d_in[8];
    float* out = (float*)d_out;

    size_t gate_smem = (size_t)(128 * 129 + 128 * 16 + 16) * sizeof(float);
    cudaFuncSetAttribute(gate_kernel, cudaFuncAttributeMaxDynamicSharedMemorySize, (int)gate_smem);
    cudaFuncSetAttribute(mlp_tc_kernel, cudaFuncAttributeMaxDynamicSharedMemorySize, MLP_SMEM);

    init_kernel<<<1, 32>>>();
    round_kernel<<<NEXP * HID * HID / 4 / 256, 256>>>((const float4*)W1, (const float4*)W2);
    gate_kernel<<<N_TOK / 128, 256, gate_smem>>>(x, Wg, bg);
    scan_kernel<<<1, 32>>>();
    scatter_kernel<<<N_TOK / 256, 256>>>();
    mlp_tc_kernel<<<dim3(512, NEXP), 256, MLP_SMEM>>>(x, b1, b2, W3, b3, out);
    (void)n_in; (void)in_sizes; (void)out_size;
}

// round 5
// speedup vs baseline: 4.7327x; 1.3379x over previous
#include <cuda_runtime.h>
#include <cuda_fp16.h>
#include <cstdint>

#define N_TOK 65536
#define DIM   128
#define HID   256
#define NEXP  16
#define NBLK  (N_TOK / 128)   // gate blocks = 512

// ---------------- device scratch ----------------
__device__ int g_expert_idx[N_TOK];
__device__ int g_perm[N_TOK];
__device__ int g_bhist[NEXP * NBLK];
__device__ int g_offsets[NEXP + 1];
__device__ int g_cursor[NEXP];
__device__ uint32_t g_W1h[NEXP * (DIM / 2) * HID];   // half2: [e][k/2][n] = (W[k][n], W[k+1][n])
__device__ uint32_t g_W2h[NEXP * (HID / 2) * HID];

// ---------------- helpers ----------------
#define MMA_F16(acc, a, b) \
    asm volatile("mma.sync.aligned.m16n8k16.row.col.f32.f16.f16.f32 " \
        "{%0,%1,%2,%3}, {%4,%5,%6,%7}, {%8,%9}, {%0,%1,%2,%3};" \
        : "+f"((acc)[0]), "+f"((acc)[1]), "+f"((acc)[2]), "+f"((acc)[3]) \
        : "r"((a)[0]), "r"((a)[1]), "r"((a)[2]), "r"((a)[3]), \
          "r"((b)[0]), "r"((b)[1]))

#define CP_ASYNC16(dst, src) \
    asm volatile("cp.async.cg.shared.global [%0], [%1], 16;" :: "r"(dst), "l"(src))
#define CP_COMMIT() asm volatile("cp.async.commit_group;" ::: "memory")
#define CP_WAIT0()  asm volatile("cp.async.wait_group 0;"  ::: "memory")

__device__ __forceinline__ uint32_t smem_u32(const void* p) {
    uint32_t a;
    asm("{ .reg .u64 t; cvta.to.shared.u64 t, %1; cvt.u32.u64 %0, t; }" : "=r"(a) : "l"(p));
    return a;
}
__device__ __forceinline__ uint32_t pack_h2(float lo, float hi) {
    __half2 h = __floats2half2_rn(lo, hi);
    return *(uint32_t*)&h;
}

// ---------------- gate: fp32-exact argmax, per-block histogram ----------------
__global__ __launch_bounds__(256) void gate_kernel(const float* __restrict__ x,
                                                   const float* __restrict__ Wg,
                                                   const float* __restrict__ bg) {
    extern __shared__ float sm[];
    float* xs  = sm;
    float* wg  = xs + 128 * 129;
    float* bgs = wg + 128 * 16;
    __shared__ int hist[NEXP];

    int tid = threadIdx.x;
    if (tid < NEXP) { hist[tid] = 0; bgs[tid] = bg[tid]; }
    for (int i = tid; i < DIM * NEXP; i += 256) wg[i] = Wg[i];

    long base = (long)blockIdx.x * 128 * DIM;
    const float4* xg = (const float4*)(x + base);
    for (int i4 = tid; i4 < 128 * DIM / 4; i4 += 256) {
        float4 v = xg[i4];
        int row = i4 >> 5;
        int c4  = i4 & 31;
        float* dst = xs + row * 129 + c4 * 4;
        dst[0] = v.x; dst[1] = v.y; dst[2] = v.z; dst[3] = v.w;
    }
    __syncthreads();

    int tcol = tid & 15;
    int trow = tid >> 4;

    float acc[8];
#pragma unroll
    for (int r = 0; r < 8; r++) acc[r] = bgs[tcol];
    for (int k = 0; k < DIM; k++) {
        float w = wg[k * NEXP + tcol];
#pragma unroll
        for (int r = 0; r < 8; r++)
            acc[r] = fmaf(xs[(trow * 8 + r) * 129 + k], w, acc[r]);
    }
#pragma unroll
    for (int r = 0; r < 8; r++) {
        float v = acc[r];
        int ei = tcol;
#pragma unroll
        for (int off = 8; off > 0; off >>= 1) {
            float ov = __shfl_xor_sync(0xffffffffu, v, off, 16);
            int   oe = __shfl_xor_sync(0xffffffffu, ei, off, 16);
            if (ov > v || (ov == v && oe < ei)) { v = ov; ei = oe; }
        }
        if (tcol == 0) {
            int t = blockIdx.x * 128 + trow * 8 + r;
            g_expert_idx[t] = ei;
            atomicAdd(&hist[ei], 1);
        }
    }
    __syncthreads();
    if (tid < NEXP) g_bhist[tid * NBLK + blockIdx.x] = hist[tid];
}

// ---------------- scan: sum per-block hists, prefix ----------------
__global__ __launch_bounds__(512) void scan_kernel() {
    __shared__ int sums[NEXP];
    int wid = threadIdx.x >> 5, lane = threadIdx.x & 31;
    int s = 0;
    for (int i = lane; i < NBLK; i += 32) s += g_bhist[wid * NBLK + i];
#pragma unroll
    for (int off = 16; off > 0; off >>= 1) s += __shfl_xor_sync(0xffffffffu, s, off);
    if (lane == 0) sums[wid] = s;
    __syncthreads();
    if (threadIdx.x == 0) {
        int run = 0;
        for (int e = 0; e < NEXP; e++) {
            g_offsets[e] = run;
            g_cursor[e]  = run;
            run += sums[e];
        }
        g_offsets[NEXP] = run;
    }
}

__global__ __launch_bounds__(256) void scatter_kernel() {
    int t = blockIdx.x * 256 + threadIdx.x;
    int e = g_expert_idx[t];
    unsigned m  = __match_any_sync(0xffffffffu, e);
    int lane    = threadIdx.x & 31;
    int leader  = __ffs(m) - 1;
    int rank    = __popc(m & ((1u << lane) - 1));
    int base    = 0;
    if (lane == leader) base = atomicAdd(&g_cursor[e], __popc(m));
    base = __shfl_sync(0xffffffffu, base, leader);
    g_perm[base + rank] = t;
}

// ---------------- pack weights: fp32 [e][k][n] -> half2 [e][k/2][n] ----------------
__global__ __launch_bounds__(256) void pack_kernel(const float* __restrict__ W1,
                                                   const float* __restrict__ W2) {
    int i = blockIdx.x * 256 + threadIdx.x;           // W2 pairs: NEXP*128*256
    {
        int e = i >> 15, r = i & 32767;
        int k2 = r >> 8, n = r & 255;
        const float* s = W2 + ((long)e * HID + 2 * k2) * HID + n;
        g_W2h[i] = pack_h2(s[0], s[HID]);
    }
    if (i < NEXP * (DIM / 2) * HID) {
        int e = i >> 14, r = i & 16383;
        int k2 = r >> 8, n = r & 255;
        const float* s = W1 + ((long)e * DIM + 2 * k2) * HID + n;
        g_W1h[i] = pack_h2(s[0], s[HID]);
    }
}

// ---------------- fp16 mma.sync grouped MLP ----------------
// 8 warps as 2(M) x 4(N); warp tile 64x64 (fm=4, fn=8), k16 per MMA.
// strides chosen conflict-free: xs 136 halfs (68 words), ws 264 words, h1 264 halfs (132 words).
#define WS_STR  264
#define XS_STRW 68
#define H1_STRW 132
#define F_WS0   0
#define F_WS1   (8 * WS_STR)
#define F_B1S   (16 * WS_STR)
#define F_B2S   (F_B1S + 256)
#define F_W3S   (F_B2S + 256)
#define F_PS    (F_W3S + 256)
#define F_UNION (F_PS + 512)
#define MLP_SMEM ((F_UNION + 128 * H1_STRW) * 4)

// stage one k16 chunk (8 pair-rows x 256 half2) of packed W into ws
__device__ __forceinline__ void cp_chunk(const uint32_t* __restrict__ W, int ch,
                                         uint32_t ws_smem, int tid) {
#pragma unroll
    for (int i = 0; i < 2; i++) {
        int f4  = tid + 256 * i;       // 512 float4s = 8 rows x 256 words
        int row = f4 >> 6;
        int c4  = f4 & 63;
        const uint32_t* src = W + (long)(ch * 8 + row) * HID + c4 * 4;
        uint32_t dst = ws_smem + (uint32_t)(row * WS_STR + c4 * 4) * 4u;
        CP_ASYNC16(dst, src);
    }
}

__global__ __launch_bounds__(256, 1) void mlp_tc_kernel(
        const float* __restrict__ x,
        const float* __restrict__ b1, const float* __restrict__ b2,
        const float* __restrict__ W3, const float* __restrict__ b3,
        float* __restrict__ out) {
    int e   = blockIdx.y;
    int beg = g_offsets[e], end = g_offsets[e + 1];
    int start = beg + blockIdx.x * 128;
    if (start >= end) return;
    int cnt = min(128, end - start);

    extern __shared__ float sm[];
    float* b1s = sm + F_B1S;
    float* b2s = sm + F_B2S;
    float* w3s = sm + F_W3S;
    float* ps  = sm + F_PS;
    uint32_t* un = (uint32_t*)(sm + F_UNION);   // xs (GEMM1 A) / h1 (GEMM2 A), half2 words
    uint32_t ws_addr[2] = { smem_u32(sm + F_WS0), smem_u32(sm + F_WS1) };
    const uint32_t* ws_ptr[2] = { (uint32_t*)(sm + F_WS0), (uint32_t*)(sm + F_WS1) };

    int tid = threadIdx.x;
    int wid = tid >> 5, lid = tid & 31;
    int g = lid >> 2, t = lid & 3;
    int wm = wid & 1;                   // rows wm*64 .. +63
    int wn = wid >> 1;                  // cols wn*64 .. +63

    b1s[tid] = b1[e * HID + tid];
    b2s[tid] = b2[e * HID + tid];
    w3s[tid] = W3[e * HID + tid];

    // gather A1 = x[perm] -> fp16 xs [128 rows][64 words, stride 68]
#pragma unroll
    for (int i = 0; i < 16; i++) {
        int f   = tid + 256 * i;        // 4096 float4s
        int row = f >> 5;
        int c4  = f & 31;
        float4 v = make_float4(0.f, 0.f, 0.f, 0.f);
        if (row < cnt) {
            int gt = g_perm[start + row];
            v = *(const float4*)(x + (long)gt * DIM + c4 * 4);
        }
        uint32_t* dst = un + row * XS_STRW + c4 * 2;
        dst[0] = pack_h2(v.x, v.y);
        dst[1] = pack_h2(v.z, v.w);
    }

    const uint32_t* W1e = g_W1h + (long)e * (DIM / 2) * HID;
    const uint32_t* W2e = g_W2h + (long)e * (HID / 2) * HID;

    float acc[4][8][4];
#pragma unroll
    for (int fm = 0; fm < 4; fm++)
#pragma unroll
        for (int fn = 0; fn < 8; fn++)
#pragma unroll
            for (int q = 0; q < 4; q++) acc[fm][fn][q] = 0.f;

    // ================= GEMM1: K = 128, 8 chunks of k16 =================
    cp_chunk(W1e, 0, ws_addr[0], tid);
    CP_COMMIT();
    __syncthreads();

#pragma unroll 1
    for (int ch = 0; ch < 8; ch++) {
        CP_WAIT0();
        __syncthreads();
        if (ch < 7) { cp_chunk(W1e, ch + 1, ws_addr[(ch + 1) & 1], tid); CP_COMMIT(); }
        const uint32_t* wsb = ws_ptr[ch & 1];

        uint32_t a[4][4];
#pragma unroll
        for (int fm = 0; fm < 4; fm++) {
            int row = wm * 64 + fm * 16 + g;
            const uint32_t* xr = un + row * XS_STRW + ch * 8 + t;
            a[fm][0] = xr[0];
            a[fm][1] = xr[8 * XS_STRW];
            a[fm][2] = xr[4];
            a[fm][3] = xr[8 * XS_STRW + 4];
        }
        uint32_t b[8][2];
        const uint32_t* wr = wsb + t * WS_STR + wn * 64 + g;
#pragma unroll
        for (int fn = 0; fn < 8; fn++) {
            b[fn][0] = wr[fn * 8];
            b[fn][1] = wr[4 * WS_STR + fn * 8];
        }
#pragma unroll
        for (int fm = 0; fm < 4; fm++)
#pragma unroll
            for (int fn = 0; fn < 8; fn++)
                MMA_F16(acc[fm][fn], a[fm], b[fn]);
    }

    __syncthreads();                    // all warps done reading xs

    // ---- epilogue 1: h1 = fp16(relu(acc + b1)) into [128][stride 132 words] ----
#pragma unroll
    for (int fm = 0; fm < 4; fm++) {
        int r = wm * 64 + fm * 16 + g;
#pragma unroll
        for (int fn = 0; fn < 8; fn++) {
            int c = wn * 64 + fn * 8 + t * 2;
            un[r * H1_STRW + c / 2] =
                pack_h2(fmaxf(acc[fm][fn][0] + b1s[c],     0.f),
                        fmaxf(acc[fm][fn][1] + b1s[c + 1], 0.f));
            un[(r + 8) * H1_STRW + c / 2] =
                pack_h2(fmaxf(acc[fm][fn][2] + b1s[c],     0.f),
                        fmaxf(acc[fm][fn][3] + b1s[c + 1], 0.f));
            acc[fm][fn][0] = 0.f; acc[fm][fn][1] = 0.f;
            acc[fm][fn][2] = 0.f; acc[fm][fn][3] = 0.f;
        }
    }
    __syncthreads();

    // ================= GEMM2: K = 256, 16 chunks of k16 =================
    cp_chunk(W2e, 0, ws_addr[0], tid);
    CP_COMMIT();

#pragma unroll 1
    for (int ch = 0; ch < 16; ch++) {
        CP_WAIT0();
        __syncthreads();
        if (ch < 15) { cp_chunk(W2e, ch + 1, ws_addr[(ch + 1) & 1], tid); CP_COMMIT(); }
        const uint32_t* wsb = ws_ptr[ch & 1];

        uint32_t a[4][4];
#pragma unroll
        for (int fm = 0; fm < 4; fm++) {
            int row = wm * 64 + fm * 16 + g;
            const uint32_t* hr = un + row * H1_STRW + ch * 8 + t;
            a[fm][0] = hr[0];
            a[fm][1] = hr[8 * H1_STRW];
            a[fm][2] = hr[4];
            a[fm][3] = hr[8 * H1_STRW + 4];
        }
        uint32_t b[8][2];
        const uint32_t* wr = wsb + t * WS_STR + wn * 64 + g;
#pragma unroll
        for (int fn = 0; fn < 8; fn++) {
            b[fn][0] = wr[fn * 8];
            b[fn][1] = wr[4 * WS_STR + fn * 8];
        }
#pragma unroll
        for (int fm = 0; fm < 4; fm++)
#pragma unroll
            for (int fn = 0; fn < 8; fn++)
                MMA_F16(acc[fm][fn], a[fm], b[fn]);
    }

    // ---- epilogue 2: y = relu(acc + b2) . w3 + b3 ----
    float part[4][2];
#pragma unroll
    for (int fm = 0; fm < 4; fm++) { part[fm][0] = 0.f; part[fm][1] = 0.f; }
#pragma unroll
    for (int fm = 0; fm < 4; fm++)
#pragma unroll
        for (int fn = 0; fn < 8; fn++) {
            int c = wn * 64 + fn * 8 + t * 2;
            part[fm][0] = fmaf(fmaxf(acc[fm][fn][0] + b2s[c],     0.f), w3s[c],     part[fm][0]);
            part[fm][0] = fmaf(fmaxf(acc[fm][fn][1] + b2s[c + 1], 0.f), w3s[c + 1], part[fm][0]);
            part[fm][1] = fmaf(fmaxf(acc[fm][fn][2] + b2s[c],     0.f), w3s[c],     part[fm][1]);
            part[fm][1] = fmaf(fmaxf(acc[fm][fn][3] + b2s[c + 1], 0.f), w3s[c + 1], part[fm][1]);
        }
#pragma unroll
    for (int fm = 0; fm < 4; fm++)
#pragma unroll
        for (int h = 0; h < 2; h++) {
            part[fm][h] += __shfl_xor_sync(0xffffffffu, part[fm][h], 1);
            part[fm][h] += __shfl_xor_sync(0xffffffffu, part[fm][h], 2);
        }
    if (t == 0) {
#pragma unroll
        for (int fm = 0; fm < 4; fm++) {
            int r = wm * 64 + fm * 16 + g;
            ps[r * 4 + wn]       = part[fm][0];
            ps[(r + 8) * 4 + wn] = part[fm][1];
        }
    }
    __syncthreads();

    if (tid < cnt)
        out[g_perm[start + tid]] = ps[tid * 4] + ps[tid * 4 + 1]
                                 + ps[tid * 4 + 2] + ps[tid * 4 + 3] + b3[e];
}

// ---------------- launch ----------------
extern "C" void kernel_launch(void* const* d_in, const int* in_sizes, int n_in,
                              void* d_out, int out_size) {
    const float* x  = (const float*)d_in[0];
    const float* Wg = (const float*)d_in[1];
    const float* bg = (const float*)d_in[2];
    const float* W1 = (const float*)d_in[3];
    const float* b1 = (const float*)d_in[4];
    const float* W2 = (const float*)d_in[5];
    const float* b2 = (const float*)d_in[6];
    const float* W3 = (const float*)d_in[7];
    const float* b3 = (const float*)d_in[8];
    float* out = (float*)d_out;

    size_t gate_smem = (size_t)(128 * 129 + 128 * 16 + 16) * sizeof(float);
    cudaFuncSetAttribute(gate_kernel, cudaFuncAttributeMaxDynamicSharedMemorySize, (int)gate_smem);
    cudaFuncSetAttribute(mlp_tc_kernel, cudaFuncAttributeMaxDynamicSharedMemorySize, MLP_SMEM);

    pack_kernel<<<NEXP * (HID / 2) * HID / 256, 256>>>(W1, W2);
    gate_kernel<<<NBLK, 256, gate_smem>>>(x, Wg, bg);
    scan_kernel<<<1, 512>>>();
    scatter_kernel<<<N_TOK / 256, 256>>>();
    mlp_tc_kernel<<<dim3(512, NEXP), 256, MLP_SMEM>>>(x, b1, b2, W3, b3, out);
    (void)n_in; (void)in_sizes; (void)out_size;
}

// round 6
// speedup vs baseline: 5.0891x; 1.0753x over previous
#include <cuda_runtime.h>
#include <cuda_fp16.h>
#include <cstdint>

#define N_TOK 65536
#define DIM   128
#define HID   256
#define NEXP  16
#define NBLK  (N_TOK / 128)   // gate blocks = 512

// ---------------- device scratch ----------------
__device__ int g_expert_idx[N_TOK];
__device__ int g_perm[N_TOK];
__device__ int g_counts[NEXP];
__device__ int g_done;
__device__ int g_offsets[NEXP + 1];
__device__ int g_cursor[NEXP];
__device__ uint32_t g_W1h[NEXP * (DIM / 2) * HID];   // half2: [e][k/2][n]
__device__ uint32_t g_W2h[NEXP * (HID / 2) * HID];

// ---------------- helpers ----------------
#define MMA_F16(acc, a, b) \
    asm volatile("mma.sync.aligned.m16n8k16.row.col.f32.f16.f16.f32 " \
        "{%0,%1,%2,%3}, {%4,%5,%6,%7}, {%8,%9}, {%0,%1,%2,%3};" \
        : "+f"((acc)[0]), "+f"((acc)[1]), "+f"((acc)[2]), "+f"((acc)[3]) \
        : "r"((a)[0]), "r"((a)[1]), "r"((a)[2]), "r"((a)[3]), \
          "r"((b)[0]), "r"((b)[1]))

#define CP_ASYNC16(dst, src) \
    asm volatile("cp.async.cg.shared.global [%0], [%1], 16;" :: "r"(dst), "l"(src))
#define CP_COMMIT() asm volatile("cp.async.commit_group;" ::: "memory")
#define CP_WAIT0()  asm volatile("cp.async.wait_group 0;"  ::: "memory")

__device__ __forceinline__ uint32_t smem_u32(const void* p) {
    uint32_t a;
    asm("{ .reg .u64 t; cvta.to.shared.u64 t, %1; cvt.u32.u64 %0, t; }" : "=r"(a) : "l"(p));
    return a;
}
__device__ __forceinline__ uint32_t pack_h2(float lo, float hi) {
    __half2 h = __floats2half2_rn(lo, hi);
    return *(uint32_t*)&h;
}

// ---------------- pack weights + seed counters (runs first every replay) ----------------
__global__ __launch_bounds__(256) void pack_kernel(const float* __restrict__ W1,
                                                   const float* __restrict__ W2) {
    int i = blockIdx.x * 256 + threadIdx.x;
    if (i < NEXP + 1) {                 // first-ever-run seed (later replays self-clean in gate)
        if (i < NEXP) g_counts[i] = g_counts[i] * 0;   // no-op shape; keep deterministic
        if (i == NEXP) g_done = g_done * 0;
    }
    {
        int e = i >> 15, r = i & 32767;
        int k2 = r >> 8, n = r & 255;
        const float* s = W2 + ((long)e * HID + 2 * k2) * HID + n;
        g_W2h[i] = pack_h2(s[0], s[HID]);
    }
    if (i < NEXP * (DIM / 2) * HID) {
        int e = i >> 14, r = i & 16383;
        int k2 = r >> 8, n = r & 255;
        const float* s = W1 + ((long)e * DIM + 2 * k2) * HID + n;
        g_W1h[i] = pack_h2(s[0], s[HID]);
    }
}

// ---------------- gate: fp32-exact argmax + last-block prefix scan ----------------
__global__ __launch_bounds__(256) void gate_kernel(const float* __restrict__ x,
                                                   const float* __restrict__ Wg,
                                                   const float* __restrict__ bg) {
    extern __shared__ float sm[];
    float* xs  = sm;
    float* wg  = xs + 128 * 129;
    float* bgs = wg + 128 * 16;
    __shared__ int hist[NEXP];
    __shared__ int is_last;

    int tid = threadIdx.x;
    if (tid < NEXP) { hist[tid] = 0; bgs[tid] = bg[tid]; }
    for (int i = tid; i < DIM * NEXP; i += 256) wg[i] = Wg[i];

    long base = (long)blockIdx.x * 128 * DIM;
    const float4* xg = (const float4*)(x + base);
    for (int i4 = tid; i4 < 128 * DIM / 4; i4 += 256) {
        float4 v = xg[i4];
        int row = i4 >> 5;
        int c4  = i4 & 31;
        float* dst = xs + row * 129 + c4 * 4;
        dst[0] = v.x; dst[1] = v.y; dst[2] = v.z; dst[3] = v.w;
    }
    __syncthreads();

    int tcol = tid & 15;
    int trow = tid >> 4;

    float acc[8];
#pragma unroll
    for (int r = 0; r < 8; r++) acc[r] = bgs[tcol];
    for (int k = 0; k < DIM; k++) {
        float w = wg[k * NEXP + tcol];
#pragma unroll
        for (int r = 0; r < 8; r++)
            acc[r] = fmaf(xs[(trow * 8 + r) * 129 + k], w, acc[r]);
    }
#pragma unroll
    for (int r = 0; r < 8; r++) {
        float v = acc[r];
        int ei = tcol;
#pragma unroll
        for (int off = 8; off > 0; off >>= 1) {
            float ov = __shfl_xor_sync(0xffffffffu, v, off, 16);
            int   oe = __shfl_xor_sync(0xffffffffu, ei, off, 16);
            if (ov > v || (ov == v && oe < ei)) { v = ov; ei = oe; }
        }
        if (tcol == 0) {
            int t = blockIdx.x * 128 + trow * 8 + r;
            g_expert_idx[t] = ei;
            atomicAdd(&hist[ei], 1);
        }
    }
    __syncthreads();
    if (tid < NEXP && hist[tid]) atomicAdd(&g_counts[tid], hist[tid]);
    __threadfence();
    __syncthreads();
    if (tid == 0) {
        int d = atomicAdd(&g_done, 1);
        is_last = (d == NBLK - 1);
    }
    __syncthreads();
    if (is_last && tid == 0) {
        int run = 0;
#pragma unroll
        for (int e = 0; e < NEXP; e++) {
            g_offsets[e] = run;
            g_cursor[e]  = run;
            run += g_counts[e];
            g_counts[e] = 0;            // self-clean for next replay
        }
        g_offsets[NEXP] = run;
        g_done = 0;
        __threadfence();
    }
}

__global__ __launch_bounds__(256) void scatter_kernel() {
    int t = blockIdx.x * 256 + threadIdx.x;
    int e = g_expert_idx[t];
    unsigned m  = __match_any_sync(0xffffffffu, e);
    int lane    = threadIdx.x & 31;
    int leader  = __ffs(m) - 1;
    int rank    = __popc(m & ((1u << lane) - 1));
    int base    = 0;
    if (lane == leader) base = atomicAdd(&g_cursor[e], __popc(m));
    base = __shfl_sync(0xffffffffu, base, leader);
    g_perm[base + rank] = t;
}

// ---------------- fp16 mma.sync grouped MLP, M=64 tiles, 2 CTAs/SM ----------------
// 8 warps as 2(M) x 4(N); warp tile 32x64 (fm=2, fn=8), k16 per MMA.
#define WS_STR  264
#define XS_STRW 68
#define H1_STRW 132
#define F_WS0   0
#define F_WS1   (8 * WS_STR)
#define F_B1S   (16 * WS_STR)
#define F_B2S   (F_B1S + 256)
#define F_W3S   (F_B2S + 256)
#define F_PS    (F_W3S + 256)
#define F_UNION (F_PS + 256)
#define MLP_SMEM ((F_UNION + 64 * H1_STRW) * 4)

__device__ __forceinline__ void cp_chunk(const uint32_t* __restrict__ W, int ch,
                                         uint32_t ws_smem, int tid) {
#pragma unroll
    for (int i = 0; i < 2; i++) {
        int f4  = tid + 256 * i;       // 512 float4s = 8 rows x 256 words
        int row = f4 >> 6;
        int c4  = f4 & 63;
        const uint32_t* src = W + (long)(ch * 8 + row) * HID + c4 * 4;
        uint32_t dst = ws_smem + (uint32_t)(row * WS_STR + c4 * 4) * 4u;
        CP_ASYNC16(dst, src);
    }
}

__global__ __launch_bounds__(256, 2) void mlp_tc_kernel(
        const float* __restrict__ x,
        const float* __restrict__ b1, const float* __restrict__ b2,
        const float* __restrict__ W3, const float* __restrict__ b3,
        float* __restrict__ out) {
    int e   = blockIdx.y;
    int beg = g_offsets[e], end = g_offsets[e + 1];
    int start = beg + blockIdx.x * 64;
    if (start >= end) return;
    int cnt = min(64, end - start);

    extern __shared__ float sm[];
    float* b1s = sm + F_B1S;
    float* b2s = sm + F_B2S;
    float* w3s = sm + F_W3S;
    float* ps  = sm + F_PS;
    uint32_t* un = (uint32_t*)(sm + F_UNION);   // xs / h1 (half2 words)
    uint32_t ws_addr[2] = { smem_u32(sm + F_WS0), smem_u32(sm + F_WS1) };
    const uint32_t* ws_ptr[2] = { (uint32_t*)(sm + F_WS0), (uint32_t*)(sm + F_WS1) };

    int tid = threadIdx.x;
    int wid = tid >> 5, lid = tid & 31;
    int g = lid >> 2, t = lid & 3;
    int wm = wid & 1;                   // rows wm*32 .. +31
    int wn = wid >> 1;                  // cols wn*64 .. +63

    b1s[tid] = b1[e * HID + tid];
    b2s[tid] = b2[e * HID + tid];
    w3s[tid] = W3[e * HID + tid];

    // gather A1 = x[perm] -> fp16 xs [64 rows][64 words, stride 68]
#pragma unroll
    for (int i = 0; i < 8; i++) {
        int f   = tid + 256 * i;        // 2048 float4s
        int row = f >> 5;
        int c4  = f & 31;
        float4 v = make_float4(0.f, 0.f, 0.f, 0.f);
        if (row < cnt) {
            int gt = g_perm[start + row];
            v = *(const float4*)(x + (long)gt * DIM + c4 * 4);
        }
        uint32_t* dst = un + row * XS_STRW + c4 * 2;
        dst[0] = pack_h2(v.x, v.y);
        dst[1] = pack_h2(v.z, v.w);
    }

    const uint32_t* W1e = g_W1h + (long)e * (DIM / 2) * HID;
    const uint32_t* W2e = g_W2h + (long)e * (HID / 2) * HID;

    float acc[2][8][4];
#pragma unroll
    for (int fm = 0; fm < 2; fm++)
#pragma unroll
        for (int fn = 0; fn < 8; fn++)
#pragma unroll
            for (int q = 0; q < 4; q++) acc[fm][fn][q] = 0.f;

    // ================= GEMM1: K = 128, 8 chunks of k16 =================
    cp_chunk(W1e, 0, ws_addr[0], tid);
    CP_COMMIT();
    __syncthreads();

#pragma unroll 1
    for (int ch = 0; ch < 8; ch++) {
        CP_WAIT0();
        __syncthreads();
        if (ch < 7) { cp_chunk(W1e, ch + 1, ws_addr[(ch + 1) & 1], tid); CP_COMMIT(); }
        const uint32_t* wsb = ws_ptr[ch & 1];

        uint32_t a[2][4];
#pragma unroll
        for (int fm = 0; fm < 2; fm++) {
            int row = wm * 32 + fm * 16 + g;
            const uint32_t* xr = un + row * XS_STRW + ch * 8 + t;
            a[fm][0] = xr[0];
            a[fm][1] = xr[8 * XS_STRW];
            a[fm][2] = xr[4];
            a[fm][3] = xr[8 * XS_STRW + 4];
        }
        uint32_t b[8][2];
        const uint32_t* wr = wsb + t * WS_STR + wn * 64 + g;
#pragma unroll
        for (int fn = 0; fn < 8; fn++) {
            b[fn][0] = wr[fn * 8];
            b[fn][1] = wr[4 * WS_STR + fn * 8];
        }
#pragma unroll
        for (int fm = 0; fm < 2; fm++)
#pragma unroll
            for (int fn = 0; fn < 8; fn++)
                MMA_F16(acc[fm][fn], a[fm], b[fn]);
    }

    __syncthreads();                    // all warps done reading xs

    // ---- epilogue 1: h1 = fp16(relu(acc + b1)), [64 rows][stride 132 words] ----
#pragma unroll
    for (int fm = 0; fm < 2; fm++) {
        int r = wm * 32 + fm * 16 + g;
#pragma unroll
        for (int fn = 0; fn < 8; fn++) {
            int c = wn * 64 + fn * 8 + t * 2;
            un[r * H1_STRW + c / 2] =
                pack_h2(fmaxf(acc[fm][fn][0] + b1s[c],     0.f),
                        fmaxf(acc[fm][fn][1] + b1s[c + 1], 0.f));
            un[(r + 8) * H1_STRW + c / 2] =
                pack_h2(fmaxf(acc[fm][fn][2] + b1s[c],     0.f),
                        fmaxf(acc[fm][fn][3] + b1s[c + 1], 0.f));
            acc[fm][fn][0] = 0.f; acc[fm][fn][1] = 0.f;
            acc[fm][fn][2] = 0.f; acc[fm][fn][3] = 0.f;
        }
    }
    __syncthreads();

    // ================= GEMM2: K = 256, 16 chunks of k16 =================
    cp_chunk(W2e, 0, ws_addr[0], tid);
    CP_COMMIT();

#pragma unroll 1
    for (int ch = 0; ch < 16; ch++) {
        CP_WAIT0();
        __syncthreads();
        if (ch < 15) { cp_chunk(W2e, ch + 1, ws_addr[(ch + 1) & 1], tid); CP_COMMIT(); }
        const uint32_t* wsb = ws_ptr[ch & 1];

        uint32_t a[2][4];
#pragma unroll
        for (int fm = 0; fm < 2; fm++) {
            int row = wm * 32 + fm * 16 + g;
            const uint32_t* hr = un + row * H1_STRW + ch * 8 + t;
            a[fm][0] = hr[0];
            a[fm][1] = hr[8 * H1_STRW];
            a[fm][2] = hr[4];
            a[fm][3] = hr[8 * H1_STRW + 4];
        }
        uint32_t b[8][2];
        const uint32_t* wr = wsb + t * WS_STR + wn * 64 + g;
#pragma unroll
        for (int fn = 0; fn < 8; fn++) {
            b[fn][0] = wr[fn * 8];
            b[fn][1] = wr[4 * WS_STR + fn * 8];
        }
#pragma unroll
        for (int fm = 0; fm < 2; fm++)
#pragma unroll
            for (int fn = 0; fn < 8; fn++)
                MMA_F16(acc[fm][fn], a[fm], b[fn]);
    }

    // ---- epilogue 2: y = relu(acc + b2) . w3 + b3 ----
    float part[2][2];
#pragma unroll
    for (int fm = 0; fm < 2; fm++) { part[fm][0] = 0.f; part[fm][1] = 0.f; }
#pragma unroll
    for (int fm = 0; fm < 2; fm++)
#pragma unroll
        for (int fn = 0; fn < 8; fn++) {
            int c = wn * 64 + fn * 8 + t * 2;
            part[fm][0] = fmaf(fmaxf(acc[fm][fn][0] + b2s[c],     0.f), w3s[c],     part[fm][0]);
            part[fm][0] = fmaf(fmaxf(acc[fm][fn][1] + b2s[c + 1], 0.f), w3s[c + 1], part[fm][0]);
            part[fm][1] = fmaf(fmaxf(acc[fm][fn][2] + b2s[c],     0.f), w3s[c],     part[fm][1]);
            part[fm][1] = fmaf(fmaxf(acc[fm][fn][3] + b2s[c + 1], 0.f), w3s[c + 1], part[fm][1]);
        }
#pragma unroll
    for (int fm = 0; fm < 2; fm++)
#pragma unroll
        for (int h = 0; h < 2; h++) {
            part[fm][h] += __shfl_xor_sync(0xffffffffu, part[fm][h], 1);
            part[fm][h] += __shfl_xor_sync(0xffffffffu, part[fm][h], 2);
        }
    if (t == 0) {
#pragma unroll
        for (int fm = 0; fm < 2; fm++) {
            int r = wm * 32 + fm * 16 + g;
            ps[r * 4 + wn]       = part[fm][0];
            ps[(r + 8) * 4 + wn] = part[fm][1];
        }
    }
    __syncthreads();

    if (tid < cnt)
        out[g_perm[start + tid]] = ps[tid * 4] + ps[tid * 4 + 1]
                                 + ps[tid * 4 + 2] + ps[tid * 4 + 3] + b3[e];
}

// ---------------- launch ----------------
extern "C" void kernel_launch(void* const* d_in, const int* in_sizes, int n_in,
                              void* d_out, int out_size) {
    const float* x  = (const float*)d_in[0];
    const float* Wg = (const float*)d_in[1];
    const float* bg = (const float*)d_in[2];
    const float* W1 = (const float*)d_in[3];
    const float* b1 = (const float*)d_in[4];
    const float* W2 = (const float*)d_in[5];
    const float* b2 = (const float*)d_in[6];
    const float* W3 = (const float*)d_in[7];
    const float* b3 = (const float*)d_in[8];
    float* out = (float*)d_out;

    size_t gate_smem = (size_t)(128 * 129 + 128 * 16 + 16) * sizeof(float);
    cudaFuncSetAttribute(gate_kernel, cudaFuncAttributeMaxDynamicSharedMemorySize, (int)gate_smem);
    cudaFuncSetAttribute(mlp_tc_kernel, cudaFuncAttributeMaxDynamicSharedMemorySize, MLP_SMEM);

    pack_kernel<<<NEXP * (HID / 2) * HID / 256, 256>>>(W1, W2);
    gate_kernel<<<NBLK, 256, gate_smem>>>(x, Wg, bg);
    scatter_kernel<<<N_TOK / 256, 256>>>();
    mlp_tc_kernel<<<dim3(1024, NEXP), 256, MLP_SMEM>>>(x, b1, b2, W3, b3, out);
    (void)n_in; (void)in_sizes; (void)out_size;
}

// round 7
// speedup vs baseline: 5.8843x; 1.1563x over previous
#include <cuda_runtime.h>
#include <cuda_fp16.h>
#include <cstdint>

#define N_TOK 65536
#define DIM   128
#define HID   256
#define NEXP  16
#define NBLK  (N_TOK / 128)   // gate blocks = 512
#define MAXTILES 1040         // sum ceil(cnt/64) <= 65536/64 + 16

// ---------------- device scratch ----------------
__device__ int g_expert_idx[N_TOK];
__device__ int g_perm[N_TOK];
__device__ int g_counts[NEXP];
__device__ int g_done;
__device__ int g_offsets[NEXP + 1];
__device__ int g_cursor[NEXP];
__device__ int g_ntiles;
__device__ int g_tile_e[MAXTILES];
__device__ int g_tile_start[MAXTILES];
__device__ uint32_t g_W1h[NEXP * (DIM / 2) * HID];   // half2: [e][k/2][n]
__device__ uint32_t g_W2h[NEXP * (HID / 2) * HID];

// ---------------- helpers ----------------
#define MMA_F16(acc, a, b) \
    asm volatile("mma.sync.aligned.m16n8k16.row.col.f32.f16.f16.f32 " \
        "{%0,%1,%2,%3}, {%4,%5,%6,%7}, {%8,%9}, {%0,%1,%2,%3};" \
        : "+f"((acc)[0]), "+f"((acc)[1]), "+f"((acc)[2]), "+f"((acc)[3]) \
        : "r"((a)[0]), "r"((a)[1]), "r"((a)[2]), "r"((a)[3]), \
          "r"((b)[0]), "r"((b)[1]))

#define CP_ASYNC16(dst, src) \
    asm volatile("cp.async.cg.shared.global [%0], [%1], 16;" :: "r"(dst), "l"(src))
#define CP_COMMIT() asm volatile("cp.async.commit_group;" ::: "memory")
#define CP_WAIT(n)  asm volatile("cp.async.wait_group %0;" :: "n"(n) : "memory")

__device__ __forceinline__ uint32_t smem_u32(const void* p) {
    uint32_t a;
    asm("{ .reg .u64 t; cvta.to.shared.u64 t, %1; cvt.u32.u64 %0, t; }" : "=r"(a) : "l"(p));
    return a;
}
__device__ __forceinline__ uint32_t pack_h2(float lo, float hi) {
    __half2 h = __floats2half2_rn(lo, hi);
    return *(uint32_t*)&h;
}

// ---------------- pack weights (first launch each replay) ----------------
__global__ __launch_bounds__(256) void pack_kernel(const float* __restrict__ W1,
                                                   const float* __restrict__ W2) {
    int i = blockIdx.x * 256 + threadIdx.x;
    {
        int e = i >> 15, r = i & 32767;
        int k2 = r >> 8, n = r & 255;
        const float* s = W2 + ((long)e * HID + 2 * k2) * HID + n;
        g_W2h[i] = pack_h2(s[0], s[HID]);
    }
    if (i < NEXP * (DIM / 2) * HID) {
        int e = i >> 14, r = i & 16383;
        int k2 = r >> 8, n = r & 255;
        const float* s = W1 + ((long)e * DIM + 2 * k2) * HID + n;
        g_W1h[i] = pack_h2(s[0], s[HID]);
    }
}

// ---------------- gate: fp32-exact argmax + last-block scan + tile table ----------------
__global__ __launch_bounds__(256) void gate_kernel(const float* __restrict__ x,
                                                   const float* __restrict__ Wg,
                                                   const float* __restrict__ bg) {
    extern __shared__ float sm[];
    float* xs  = sm;
    float* wg  = xs + 128 * 129;
    float* bgs = wg + 128 * 16;
    __shared__ int hist[NEXP];
    __shared__ int tile_pre[NEXP];
    __shared__ int is_last;

    int tid = threadIdx.x;
    if (tid < NEXP) { hist[tid] = 0; bgs[tid] = bg[tid]; }
    for (int i = tid; i < DIM * NEXP; i += 256) wg[i] = Wg[i];

    long base = (long)blockIdx.x * 128 * DIM;
    const float4* xg = (const float4*)(x + base);
    for (int i4 = tid; i4 < 128 * DIM / 4; i4 += 256) {
        float4 v = xg[i4];
        int row = i4 >> 5;
        int c4  = i4 & 31;
        float* dst = xs + row * 129 + c4 * 4;
        dst[0] = v.x; dst[1] = v.y; dst[2] = v.z; dst[3] = v.w;
    }
    __syncthreads();

    int tcol = tid & 15;
    int trow = tid >> 4;

    float acc[8];
#pragma unroll
    for (int r = 0; r < 8; r++) acc[r] = bgs[tcol];
    for (int k = 0; k < DIM; k++) {
        float w = wg[k * NEXP + tcol];
#pragma unroll
        for (int r = 0; r < 8; r++)
            acc[r] = fmaf(xs[(trow * 8 + r) * 129 + k], w, acc[r]);
    }
#pragma unroll
    for (int r = 0; r < 8; r++) {
        float v = acc[r];
        int ei = tcol;
#pragma unroll
        for (int off = 8; off > 0; off >>= 1) {
            float ov = __shfl_xor_sync(0xffffffffu, v, off, 16);
            int   oe = __shfl_xor_sync(0xffffffffu, ei, off, 16);
            if (ov > v || (ov == v && oe < ei)) { v = ov; ei = oe; }
        }
        if (tcol == 0) {
            int t = blockIdx.x * 128 + trow * 8 + r;
            g_expert_idx[t] = ei;
            atomicAdd(&hist[ei], 1);
        }
    }
    __syncthreads();
    if (tid < NEXP && hist[tid]) atomicAdd(&g_counts[tid], hist[tid]);
    __threadfence();
    __syncthreads();
    if (tid == 0) {
        int d = atomicAdd(&g_done, 1);
        is_last = (d == NBLK - 1);
    }
    __syncthreads();
    if (is_last) {
        if (tid == 0) {
            int run = 0, trun = 0;
#pragma unroll
            for (int e = 0; e < NEXP; e++) {
                int c = g_counts[e];
                g_offsets[e] = run;
                g_cursor[e]  = run;
                tile_pre[e]  = trun;
                run  += c;
                trun += (c + 63) >> 6;
                g_counts[e] = 0;            // self-clean for next replay
            }
            g_offsets[NEXP] = run;
            g_ntiles = trun;
            g_done = 0;
        }
        __syncthreads();
        if (tid < NEXP) {
            int e = tid;
            int beg = g_offsets[e], cnt = g_offsets[e + 1] - beg;
            int nt = (cnt + 63) >> 6, tp = tile_pre[e];
            for (int i = 0; i < nt; i++) {
                g_tile_e[tp + i]     = e;
                g_tile_start[tp + i] = beg + 64 * i;
            }
        }
        __threadfence();
    }
}

__global__ __launch_bounds__(256) void scatter_kernel() {
    int t = blockIdx.x * 256 + threadIdx.x;
    int e = g_expert_idx[t];
    unsigned m  = __match_any_sync(0xffffffffu, e);
    int lane    = threadIdx.x & 31;
    int leader  = __ffs(m) - 1;
    int rank    = __popc(m & ((1u << lane) - 1));
    int base    = 0;
    if (lane == leader) base = atomicAdd(&g_cursor[e], __popc(m));
    base = __shfl_sync(0xffffffffu, base, leader);
    g_perm[base + rank] = t;
}

// ---------------- fp16 mma.sync grouped MLP: M=64, 2 CTAs/SM, 4-stage pipeline ----------------
// 8 warps as 2(M) x 4(N); warp tile 32x64 (fm=2, fn=8), k16 per MMA.
// Unified 24-chunk stream: chunks 0..7 = W1 (GEMM1), 8..23 = W2 (GEMM2).
#define WS_STR  264
#define XS_STRW 68
#define H1_STRW 132
#define NCHUNK  24
#define F_WS    0
#define WS_STAGE (8 * WS_STR)              // words per stage
#define F_B1S   (4 * WS_STAGE)             // 8448
#define F_B2S   (F_B1S + 256)
#define F_W3S   (F_B2S + 256)
#define F_PS    (F_W3S + 256)
#define F_UNION (F_PS + 256)
#define MLP_SMEM ((F_UNION + 64 * H1_STRW) * 4)

// stage one k16 chunk (8 pair-rows x 256 half2) into a ws stage
__device__ __forceinline__ void cp_chunk8(const uint32_t* __restrict__ src_base,
                                          uint32_t ws_smem, int tid) {
#pragma unroll
    for (int i = 0; i < 2; i++) {
        int f4  = tid + 256 * i;       // 512 float4s = 8 rows x 256 words
        int row = f4 >> 6;
        int c4  = f4 & 63;
        CP_ASYNC16(ws_smem + (uint32_t)(row * WS_STR + c4 * 4) * 4u,
                   src_base + (long)row * HID + c4 * 4);
    }
}

__global__ __launch_bounds__(256, 2) void mlp_tc_kernel(
        const float* __restrict__ x,
        const float* __restrict__ b1, const float* __restrict__ b2,
        const float* __restrict__ W3, const float* __restrict__ b3,
        float* __restrict__ out) {
    int tile = blockIdx.x;
    if (tile >= g_ntiles) return;
    int e     = g_tile_e[tile];
    int start = g_tile_start[tile];
    int cnt   = min(64, g_offsets[e + 1] - start);

    extern __shared__ float sm[];
    float* b1s = sm + F_B1S;
    float* b2s = sm + F_B2S;
    float* w3s = sm + F_W3S;
    float* ps  = sm + F_PS;
    uint32_t* un = (uint32_t*)(sm + F_UNION);   // xs (GEMM1 A) / h1 (GEMM2 A)
    uint32_t ws0 = smem_u32(sm + F_WS);
    const uint32_t* wsw = (const uint32_t*)(sm + F_WS);

    int tid = threadIdx.x;
    int wid = tid >> 5, lid = tid & 31;
    int g = lid >> 2, t = lid & 3;
    int wm = wid & 1;                   // rows wm*32 .. +31
    int wn = wid >> 1;                  // cols wn*64 .. +63

    b1s[tid] = b1[e * HID + tid];
    b2s[tid] = b2[e * HID + tid];
    w3s[tid] = W3[e * HID + tid];

    // gather A1 = x[perm] -> fp16 xs [64 rows][64 words, stride 68]
#pragma unroll
    for (int i = 0; i < 8; i++) {
        int f   = tid + 256 * i;
        int row = f >> 5;
        int c4  = f & 31;
        float4 v = make_float4(0.f, 0.f, 0.f, 0.f);
        if (row < cnt) {
            int gt = g_perm[start + row];
            v = *(const float4*)(x + (long)gt * DIM + c4 * 4);
        }
        uint32_t* dst = un + row * XS_STRW + c4 * 2;
        dst[0] = pack_h2(v.x, v.y);
        dst[1] = pack_h2(v.z, v.w);
    }

    const uint32_t* W1e = g_W1h + (long)e * (DIM / 2) * HID;
    const uint32_t* W2e = g_W2h + (long)e * (HID / 2) * HID;

    float acc[2][8][4];
#pragma unroll
    for (int fm = 0; fm < 2; fm++)
#pragma unroll
        for (int fn = 0; fn < 8; fn++)
#pragma unroll
            for (int q = 0; q < 4; q++) acc[fm][fn][q] = 0.f;

    // ---- prologue: prefetch chunks 0,1,2 ----
#pragma unroll
    for (int p = 0; p < 3; p++) {
        const uint32_t* src = (p < 8) ? (W1e + (long)p * 8 * HID)
                                      : (W2e + (long)(p - 8) * 8 * HID);
        cp_chunk8(src, ws0 + (uint32_t)((p & 3) * WS_STAGE) * 4u, tid);
        CP_COMMIT();
    }
    __syncthreads();                    // xs visible to all warps

    // ---- unified 24-chunk mainloop ----
#pragma unroll 1
    for (int ch = 0; ch < NCHUNK; ch++) {
        if (ch < NCHUNK - 2)      CP_WAIT(2);
        else if (ch == NCHUNK - 2) CP_WAIT(1);
        else                       CP_WAIT(0);
        __syncthreads();
        if (ch + 3 < NCHUNK) {
            int p = ch + 3;
            const uint32_t* src = (p < 8) ? (W1e + (long)p * 8 * HID)
                                          : (W2e + (long)(p - 8) * 8 * HID);
            cp_chunk8(src, ws0 + (uint32_t)((p & 3) * WS_STAGE) * 4u, tid);
            CP_COMMIT();
        }

        if (ch == 8) {
            // ---- epilogue 1: h1 = fp16(relu(acc + b1)) over the union region ----
            // (all warps are past compute of chunk 7 thanks to the sync above)
#pragma unroll
            for (int fm = 0; fm < 2; fm++) {
                int r = wm * 32 + fm * 16 + g;
#pragma unroll
                for (int fn = 0; fn < 8; fn++) {
                    int c = wn * 64 + fn * 8 + t * 2;
                    un[r * H1_STRW + c / 2] =
                        pack_h2(fmaxf(acc[fm][fn][0] + b1s[c],     0.f),
                                fmaxf(acc[fm][fn][1] + b1s[c + 1], 0.f));
                    un[(r + 8) * H1_STRW + c / 2] =
                        pack_h2(fmaxf(acc[fm][fn][2] + b1s[c],     0.f),
                                fmaxf(acc[fm][fn][3] + b1s[c + 1], 0.f));
                    acc[fm][fn][0] = 0.f; acc[fm][fn][1] = 0.f;
                    acc[fm][fn][2] = 0.f; acc[fm][fn][3] = 0.f;
                }
            }
            __syncthreads();            // h1 visible before GEMM2 reads it
        }

        const uint32_t* wsb = wsw + (ch & 3) * WS_STAGE;
        uint32_t a[2][4];
        if (ch < 8) {
#pragma unroll
            for (int fm = 0; fm < 2; fm++) {
                int row = wm * 32 + fm * 16 + g;
                const uint32_t* xr = un + row * XS_STRW + ch * 8 + t;
                a[fm][0] = xr[0];
                a[fm][1] = xr[8 * XS_STRW];
                a[fm][2] = xr[4];
                a[fm][3] = xr[8 * XS_STRW + 4];
            }
        } else {
#pragma unroll
            for (int fm = 0; fm < 2; fm++) {
                int row = wm * 32 + fm * 16 + g;
                const uint32_t* hr = un + row * H1_STRW + (ch - 8) * 8 + t;
                a[fm][0] = hr[0];
                a[fm][1] = hr[8 * H1_STRW];
                a[fm][2] = hr[4];
                a[fm][3] = hr[8 * H1_STRW + 4];
            }
        }
        uint32_t b[8][2];
        const uint32_t* wr = wsb + t * WS_STR + wn * 64 + g;
#pragma unroll
        for (int fn = 0; fn < 8; fn++) {
            b[fn][0] = wr[fn * 8];
            b[fn][1] = wr[4 * WS_STR + fn * 8];
        }
#pragma unroll
        for (int fm = 0; fm < 2; fm++)
#pragma unroll
            for (int fn = 0; fn < 8; fn++)
                MMA_F16(acc[fm][fn], a[fm], b[fn]);
    }

    // ---- epilogue 2: y = relu(acc + b2) . w3 + b3 ----
    float part[2][2];
#pragma unroll
    for (int fm = 0; fm < 2; fm++) { part[fm][0] = 0.f; part[fm][1] = 0.f; }
#pragma unroll
    for (int fm = 0; fm < 2; fm++)
#pragma unroll
        for (int fn = 0; fn < 8; fn++) {
            int c = wn * 64 + fn * 8 + t * 2;
            part[fm][0] = fmaf(fmaxf(acc[fm][fn][0] + b2s[c],     0.f), w3s[c],     part[fm][0]);
            part[fm][0] = fmaf(fmaxf(acc[fm][fn][1] + b2s[c + 1], 0.f), w3s[c + 1], part[fm][0]);
            part[fm][1] = fmaf(fmaxf(acc[fm][fn][2] + b2s[c],     0.f), w3s[c],     part[fm][1]);
            part[fm][1] = fmaf(fmaxf(acc[fm][fn][3] + b2s[c + 1], 0.f), w3s[c + 1], part[fm][1]);
        }
#pragma unroll
    for (int fm = 0; fm < 2; fm++)
#pragma unroll
        for (int h = 0; h < 2; h++) {
            part[fm][h] += __shfl_xor_sync(0xffffffffu, part[fm][h], 1);
            part[fm][h] += __shfl_xor_sync(0xffffffffu, part[fm][h], 2);
        }
    if (t == 0) {
#pragma unroll
        for (int fm = 0; fm < 2; fm++) {
            int r = wm * 32 + fm * 16 + g;
            ps[r * 4 + wn]       = part[fm][0];
            ps[(r + 8) * 4 + wn] = part[fm][1];
        }
    }
    __syncthreads();

    if (tid < cnt)
        out[g_perm[start + tid]] = ps[tid * 4] + ps[tid * 4 + 1]
                                 + ps[tid * 4 + 2] + ps[tid * 4 + 3] + b3[e];
}

// ---------------- launch ----------------
extern "C" void kernel_launch(void* const* d_in, const int* in_sizes, int n_in,
                              void* d_out, int out_size) {
    const float* x  = (const float*)d_in[0];
    const float* Wg = (const float*)d_in[1];
    const float* bg = (const float*)d_in[2];
    const float* W1 = (const float*)d_in[3];
    const float* b1 = (const float*)d_in[4];
    const float* W2 = (const float*)d_in[5];
    const float* b2 = (const float*)d_in[6];
    const float* W3 = (const float*)d_in[7];
    const float* b3 = (const float*)d_in[8];
    float* out = (float*)d_out;

    size_t gate_smem = (size_t)(128 * 129 + 128 * 16 + 16) * sizeof(float);
    cudaFuncSetAttribute(gate_kernel, cudaFuncAttributeMaxDynamicSharedMemorySize, (int)gate_smem);
    cudaFuncSetAttribute(mlp_tc_kernel, cudaFuncAttributeMaxDynamicSharedMemorySize, MLP_SMEM);

    pack_kernel<<<NEXP * (HID / 2) * HID / 256, 256>>>(W1, W2);
    gate_kernel<<<NBLK, 256, gate_smem>>>(x, Wg, bg);
    scatter_kernel<<<N_TOK / 256, 256>>>();
    mlp_tc_kernel<<<MAXTILES, 256, MLP_SMEM>>>(x, b1, b2, W3, b3, out);
    (void)n_in; (void)in_sizes; (void)out_size;
}

// round 8
// speedup vs baseline: 6.1501x; 1.0452x over previous
#include <cuda_runtime.h>
#include <cuda_fp16.h>
#include <cstdint>

#define N_TOK 65536
#define DIM   128
#define HID   256
#define NEXP  16
#define NBLK  (N_TOK / 128)
#define MAXTILES 1040

// ---------------- device scratch ----------------
__device__ int g_expert_idx[N_TOK];
__device__ int g_perm[N_TOK];
__device__ int g_counts[NEXP];
__device__ int g_done;
__device__ int g_offsets[NEXP + 1];
__device__ int g_cursor[NEXP];
__device__ int g_ntiles;
__device__ int g_tile_e[MAXTILES];
__device__ int g_tile_start[MAXTILES];
// packed fp16 weights, LDS.64-friendly: [e][chunk16][t(0..3)][n(0..255)][w(0..1)]
// word(e,c,t,n,0) = (W[c*16+2t][n],   W[c*16+2t+1][n])
// word(e,c,t,n,1) = (W[c*16+2t+8][n], W[c*16+2t+9][n])
__device__ uint32_t g_W1p[NEXP * 8 * 4 * 512];    // 8 chunk16s
__device__ uint32_t g_W2p[NEXP * 16 * 4 * 512];   // 16 chunk16s

// ---------------- helpers ----------------
#define MMA_F16(acc, a, b) \
    asm volatile("mma.sync.aligned.m16n8k16.row.col.f32.f16.f16.f32 " \
        "{%0,%1,%2,%3}, {%4,%5,%6,%7}, {%8,%9}, {%0,%1,%2,%3};" \
        : "+f"((acc)[0]), "+f"((acc)[1]), "+f"((acc)[2]), "+f"((acc)[3]) \
        : "r"((a)[0]), "r"((a)[1]), "r"((a)[2]), "r"((a)[3]), \
          "r"((b)[0]), "r"((b)[1]))

#define CP_ASYNC16(dst, src) \
    asm volatile("cp.async.cg.shared.global [%0], [%1], 16;" :: "r"(dst), "l"(src))
#define CP_COMMIT() asm volatile("cp.async.commit_group;" ::: "memory")
#define CP_WAIT(n)  asm volatile("cp.async.wait_group %0;" :: "n"(n) : "memory")

__device__ __forceinline__ uint32_t smem_u32(const void* p) {
    uint32_t a;
    asm("{ .reg .u64 t; cvta.to.shared.u64 t, %1; cvt.u32.u64 %0, t; }" : "=r"(a) : "l"(p));
    return a;
}
__device__ __forceinline__ uint32_t pack_h2(float lo, float hi) {
    __half2 h = __floats2half2_rn(lo, hi);
    return *(uint32_t*)&h;
}

// ---------------- pack weights into LDS.64 layout ----------------
__global__ __launch_bounds__(256) void pack_kernel(const float* __restrict__ W1,
                                                   const float* __restrict__ W2) {
    int i = blockIdx.x * 256 + threadIdx.x;           // over NEXP*32768 (W2 words)
    {
        int e = i >> 15, r = i & 32767;
        int c = r >> 11, rr = r & 2047;
        int t = rr >> 9, q = rr & 511;
        int n = q >> 1,  w = q & 1;
        int k = c * 16 + 2 * t + 8 * w;
        const float* s = W2 + ((long)e * HID + k) * HID + n;
        g_W2p[i] = pack_h2(s[0], s[HID]);
    }
    if (i < NEXP * 16384) {
        int e = i >> 14, r = i & 16383;
        int c = r >> 11, rr = r & 2047;
        int t = rr >> 9, q = rr & 511;
        int n = q >> 1,  w = q & 1;
        int k = c * 16 + 2 * t + 8 * w;
        const float* s = W1 + ((long)e * DIM + k) * HID + n;
        g_W1p[i] = pack_h2(s[0], s[HID]);
    }
}

// ---------------- gate: fp32-exact argmax (vectorized) + last-block scan ----------------
#define GX_STR 132
__global__ __launch_bounds__(256) void gate_kernel(const float* __restrict__ x,
                                                   const float* __restrict__ Wg,
                                                   const float* __restrict__ bg) {
    extern __shared__ float sm[];
    float* xs  = sm;                         // 128 x 132
    float* wgT = xs + 128 * GX_STR;          // 16 x 132 (transposed: [e][k])
    float* bgs = wgT + 16 * GX_STR;          // 16
    __shared__ int hist[NEXP];
    __shared__ int tile_pre[NEXP];
    __shared__ int is_last;

    int tid = threadIdx.x;
    if (tid < NEXP) { hist[tid] = 0; bgs[tid] = bg[tid]; }
    for (int i = tid; i < DIM * NEXP; i += 256) {
        int k = i >> 4, e2 = i & 15;
        wgT[e2 * GX_STR + k] = Wg[i];
    }

    long base = (long)blockIdx.x * 128 * DIM;
    const float4* xg = (const float4*)(x + base);
    for (int i4 = tid; i4 < 128 * DIM / 4; i4 += 256) {
        float4 v = xg[i4];
        int row = i4 >> 5;
        int c4  = i4 & 31;
        *(float4*)(xs + row * GX_STR + c4 * 4) = v;
    }
    __syncthreads();

    int tcol = tid & 15;
    int trow = tid >> 4;

    float acc[8];
#pragma unroll
    for (int r = 0; r < 8; r++) acc[r] = bgs[tcol];
#pragma unroll 4
    for (int k = 0; k < DIM; k += 4) {
        float4 wv = *(const float4*)(wgT + tcol * GX_STR + k);
#pragma unroll
        for (int r = 0; r < 8; r++) {
            float4 xv = *(const float4*)(xs + (trow * 8 + r) * GX_STR + k);
            acc[r] = fmaf(xv.x, wv.x, acc[r]);
            acc[r] = fmaf(xv.y, wv.y, acc[r]);
            acc[r] = fmaf(xv.z, wv.z, acc[r]);
            acc[r] = fmaf(xv.w, wv.w, acc[r]);
        }
    }
#pragma unroll
    for (int r = 0; r < 8; r++) {
        float v = acc[r];
        int ei = tcol;
#pragma unroll
        for (int off = 8; off > 0; off >>= 1) {
            float ov = __shfl_xor_sync(0xffffffffu, v, off, 16);
            int   oe = __shfl_xor_sync(0xffffffffu, ei, off, 16);
            if (ov > v || (ov == v && oe < ei)) { v = ov; ei = oe; }
        }
        if (tcol == 0) {
            int t = blockIdx.x * 128 + trow * 8 + r;
            g_expert_idx[t] = ei;
            atomicAdd(&hist[ei], 1);
        }
    }
    __syncthreads();
    if (tid < NEXP && hist[tid]) atomicAdd(&g_counts[tid], hist[tid]);
    __threadfence();
    __syncthreads();
    if (tid == 0) {
        int d = atomicAdd(&g_done, 1);
        is_last = (d == NBLK - 1);
    }
    __syncthreads();
    if (is_last) {
        if (tid == 0) {
            int run = 0, trun = 0;
#pragma unroll
            for (int e = 0; e < NEXP; e++) {
                int c = g_counts[e];
                g_offsets[e] = run;
                g_cursor[e]  = run;
                tile_pre[e]  = trun;
                run  += c;
                trun += (c + 63) >> 6;
                g_counts[e] = 0;
            }
            g_offsets[NEXP] = run;
            g_ntiles = trun;
            g_done = 0;
        }
        __syncthreads();
        if (tid < NEXP) {
            int e = tid;
            int beg = g_offsets[e], cnt = g_offsets[e + 1] - beg;
            int nt = (cnt + 63) >> 6, tp = tile_pre[e];
            for (int i = 0; i < nt; i++) {
                g_tile_e[tp + i]     = e;
                g_tile_start[tp + i] = beg + 64 * i;
            }
        }
        __threadfence();
    }
}

__global__ __launch_bounds__(256) void scatter_kernel() {
    int t = blockIdx.x * 256 + threadIdx.x;
    int e = g_expert_idx[t];
    unsigned m  = __match_any_sync(0xffffffffu, e);
    int lane    = threadIdx.x & 31;
    int leader  = __ffs(m) - 1;
    int rank    = __popc(m & ((1u << lane) - 1));
    int base    = 0;
    if (lane == leader) base = atomicAdd(&g_cursor[e], __popc(m));
    base = __shfl_sync(0xffffffffu, base, leader);
    g_perm[base + rank] = t;
}

// ---------------- fp16 mma.sync grouped MLP: M=64, k32 chunks, 4 stages ----------------
// 8 warps as 2(M) x 4(N); warp tile 32x64 (fm=2, fn=8).
// 12 chunks of k=32: 0..3 = W1 (GEMM1), 4..11 = W2 (GEMM2).
// Stage layout: [kk(0..1)*4 + t(0..3)] rows of 512 words, stride 520 (conflict-free LDS.64).
#define XS_STRW 68
#define H1_STRW 132
#define NCH 12
#define WROW 520
#define WS_STAGE (8 * WROW)                 // 4160 words
#define F_WS    0
#define F_B1S   (4 * WS_STAGE)              // 16640
#define F_B2S   (F_B1S + 256)
#define F_W3S   (F_B2S + 256)
#define F_PS    (F_W3S + 256)
#define F_UNION (F_PS + 256)
#define MLP_SMEM ((F_UNION + 64 * H1_STRW) * 4)

__device__ __forceinline__ void cp_chunk32(const uint32_t* __restrict__ src_base,
                                           uint32_t ws_smem, int tid) {
#pragma unroll
    for (int i = 0; i < 4; i++) {
        int f   = tid + 256 * i;       // 0..1023 float4s = 8 rows x 512 words
        int row = f >> 7;
        int c4  = f & 127;
        CP_ASYNC16(ws_smem + (uint32_t)(row * WROW + c4 * 4) * 4u,
                   src_base + (long)row * 512 + c4 * 4);
    }
}

__global__ __launch_bounds__(256, 2) void mlp_tc_kernel(
        const float* __restrict__ x,
        const float* __restrict__ b1, const float* __restrict__ b2,
        const float* __restrict__ W3, const float* __restrict__ b3,
        float* __restrict__ out) {
    int tile = blockIdx.x;
    if (tile >= g_ntiles) return;
    int e     = g_tile_e[tile];
    int start = g_tile_start[tile];
    int cnt   = min(64, g_offsets[e + 1] - start);

    extern __shared__ float sm[];
    float* b1s = sm + F_B1S;
    float* b2s = sm + F_B2S;
    float* w3s = sm + F_W3S;
    float* ps  = sm + F_PS;
    uint32_t* un = (uint32_t*)(sm + F_UNION);
    uint32_t ws0 = smem_u32(sm + F_WS);
    const uint32_t* wsw = (const uint32_t*)(sm + F_WS);

    int tid = threadIdx.x;
    int wid = tid >> 5, lid = tid & 31;
    int g = lid >> 2, t = lid & 3;
    int wm = wid & 1;
    int wn = wid >> 1;

    b1s[tid] = b1[e * HID + tid];
    b2s[tid] = b2[e * HID + tid];
    w3s[tid] = W3[e * HID + tid];

    // gather A1 = x[perm] -> fp16 xs [64 rows][64 words, stride 68]
#pragma unroll
    for (int i = 0; i < 8; i++) {
        int f   = tid + 256 * i;
        int row = f >> 5;
        int c4  = f & 31;
        float4 v = make_float4(0.f, 0.f, 0.f, 0.f);
        if (row < cnt) {
            int gt = g_perm[start + row];
            v = *(const float4*)(x + (long)gt * DIM + c4 * 4);
        }
        uint32_t* dst = un + row * XS_STRW + c4 * 2;
        dst[0] = pack_h2(v.x, v.y);
        dst[1] = pack_h2(v.z, v.w);
    }

    const uint32_t* W1e = g_W1p + (long)e * 16384;
    const uint32_t* W2e = g_W2p + (long)e * 32768;

    float acc[2][8][4];
#pragma unroll
    for (int fm = 0; fm < 2; fm++)
#pragma unroll
        for (int fn = 0; fn < 8; fn++)
#pragma unroll
            for (int q = 0; q < 4; q++) acc[fm][fn][q] = 0.f;

    // prologue: prefetch chunk32s 0,1,2
#pragma unroll
    for (int p = 0; p < 3; p++) {
        const uint32_t* src = (p < 4) ? (W1e + (long)p * 4096)
                                      : (W2e + (long)(p - 4) * 4096);
        cp_chunk32(src, ws0 + (uint32_t)((p & 3) * WS_STAGE) * 4u, tid);
        CP_COMMIT();
    }
    __syncthreads();

#pragma unroll 1
    for (int ch = 0; ch < NCH; ch++) {
        if (ch < NCH - 2)       CP_WAIT(2);
        else if (ch == NCH - 2) CP_WAIT(1);
        else                    CP_WAIT(0);
        __syncthreads();
        if (ch + 3 < NCH) {
            int p = ch + 3;
            const uint32_t* src = (p < 4) ? (W1e + (long)p * 4096)
                                          : (W2e + (long)(p - 4) * 4096);
            cp_chunk32(src, ws0 + (uint32_t)((p & 3) * WS_STAGE) * 4u, tid);
            CP_COMMIT();
        }

        if (ch == 4) {
            // epilogue 1: h1 = fp16(relu(acc + b1)) into union (stride 132 words)
#pragma unroll
            for (int fm = 0; fm < 2; fm++) {
                int r = wm * 32 + fm * 16 + g;
#pragma unroll
                for (int fn = 0; fn < 8; fn++) {
                    int c = wn * 64 + fn * 8 + t * 2;
                    un[r * H1_STRW + c / 2] =
                        pack_h2(fmaxf(acc[fm][fn][0] + b1s[c],     0.f),
                                fmaxf(acc[fm][fn][1] + b1s[c + 1], 0.f));
                    un[(r + 8) * H1_STRW + c / 2] =
                        pack_h2(fmaxf(acc[fm][fn][2] + b1s[c],     0.f),
                                fmaxf(acc[fm][fn][3] + b1s[c + 1], 0.f));
                    acc[fm][fn][0] = 0.f; acc[fm][fn][1] = 0.f;
                    acc[fm][fn][2] = 0.f; acc[fm][fn][3] = 0.f;
                }
            }
            __syncthreads();
        }

        const uint32_t* stg = wsw + (ch & 3) * WS_STAGE;
#pragma unroll
        for (int kk = 0; kk < 2; kk++) {
            uint32_t a[2][4];
            if (ch < 4) {
#pragma unroll
                for (int fm = 0; fm < 2; fm++) {
                    int row = wm * 32 + fm * 16 + g;
                    const uint32_t* xr = un + row * XS_STRW + ch * 16 + kk * 8 + t;
                    a[fm][0] = xr[0];
                    a[fm][1] = xr[8 * XS_STRW];
                    a[fm][2] = xr[4];
                    a[fm][3] = xr[8 * XS_STRW + 4];
                }
            } else {
#pragma unroll
                for (int fm = 0; fm < 2; fm++) {
                    int row = wm * 32 + fm * 16 + g;
                    const uint32_t* hr = un + row * H1_STRW + (ch - 4) * 16 + kk * 8 + t;
                    a[fm][0] = hr[0];
                    a[fm][1] = hr[8 * H1_STRW];
                    a[fm][2] = hr[4];
                    a[fm][3] = hr[8 * H1_STRW + 4];
                }
            }
            uint32_t b[8][2];
            const uint2* wr = (const uint2*)(stg + (kk * 4 + t) * WROW + (wn * 64 + g) * 2);
#pragma unroll
            for (int fn = 0; fn < 8; fn++) {
                uint2 bv = wr[fn * 8];            // 16 words = 8 uint2 apart
                b[fn][0] = bv.x;
                b[fn][1] = bv.y;
            }
#pragma unroll
            for (int fm = 0; fm < 2; fm++)
#pragma unroll
                for (int fn = 0; fn < 8; fn++)
                    MMA_F16(acc[fm][fn], a[fm], b[fn]);
        }
    }

    // epilogue 2: y = relu(acc + b2) . w3 + b3
    float part[2][2];
#pragma unroll
    for (int fm = 0; fm < 2; fm++) { part[fm][0] = 0.f; part[fm][1] = 0.f; }
#pragma unroll
    for (int fm = 0; fm < 2; fm++)
#pragma unroll
        for (int fn = 0; fn < 8; fn++) {
            int c = wn * 64 + fn * 8 + t * 2;
            part[fm][0] = fmaf(fmaxf(acc[fm][fn][0] + b2s[c],     0.f), w3s[c],     part[fm][0]);
            part[fm][0] = fmaf(fmaxf(acc[fm][fn][1] + b2s[c + 1], 0.f), w3s[c + 1], part[fm][0]);
            part[fm][1] = fmaf(fmaxf(acc[fm][fn][2] + b2s[c],     0.f), w3s[c],     part[fm][1]);
            part[fm][1] = fmaf(fmaxf(acc[fm][fn][3] + b2s[c + 1], 0.f), w3s[c + 1], part[fm][1]);
        }
#pragma unroll
    for (int fm = 0; fm < 2; fm++)
#pragma unroll
        for (int h = 0; h < 2; h++) {
            part[fm][h] += __shfl_xor_sync(0xffffffffu, part[fm][h], 1);
            part[fm][h] += __shfl_xor_sync(0xffffffffu, part[fm][h], 2);
        }
    if (t == 0) {
#pragma unroll
        for (int fm = 0; fm < 2; fm++) {
            int r = wm * 32 + fm * 16 + g;
            ps[r * 4 + wn]       = part[fm][0];
            ps[(r + 8) * 4 + wn] = part[fm][1];
        }
    }
    __syncthreads();

    if (tid < cnt)
        out[g_perm[start + tid]] = ps[tid * 4] + ps[tid * 4 + 1]
                                 + ps[tid * 4 + 2] + ps[tid * 4 + 3] + b3[e];
}

// ---------------- launch ----------------
extern "C" void kernel_launch(void* const* d_in, const int* in_sizes, int n_in,
                              void* d_out, int out_size) {
    const float* x  = (const float*)d_in[0];
    const float* Wg = (const float*)d_in[1];
    const float* bg = (const float*)d_in[2];
    const float* W1 = (const float*)d_in[3];
    const float* b1 = (const float*)d_in[4];
    const float* W2 = (const float*)d_in[5];
    const float* b2 = (const float*)d_in[6];
    const float* W3 = (const float*)d_in[7];
    const float* b3 = (const float*)d_in[8];
    float* out = (float*)d_out;

    size_t gate_smem = (size_t)(128 * GX_STR + 16 * GX_STR + 16) * sizeof(float);
    cudaFuncSetAttribute(gate_kernel, cudaFuncAttributeMaxDynamicSharedMemorySize, (int)gate_smem);
    cudaFuncSetAttribute(mlp_tc_kernel, cudaFuncAttributeMaxDynamicSharedMemorySize, MLP_SMEM);

    pack_kernel<<<NEXP * 32768 / 256, 256>>>(W1, W2);
    gate_kernel<<<NBLK, 256, gate_smem>>>(x, Wg, bg);
    scatter_kernel<<<N_TOK / 256, 256>>>();
    mlp_tc_kernel<<<MAXTILES, 256, MLP_SMEM>>>(x, b1, b2, W3, b3, out);
    (void)n_in; (void)in_sizes; (void)out_size;
}

// round 9
// speedup vs baseline: 6.1921x; 1.0068x over previous
#include <cuda_runtime.h>
#include <cuda_fp16.h>
#include <cstdint>

#define N_TOK 65536
#define DIM   128
#define HID   256
#define NEXP  16
#define NBLK  (N_TOK / 128)
#define MAXTILES 1040
#define MLP_GRID 296

// ---------------- device scratch ----------------
__device__ int g_expert_idx[N_TOK];
__device__ int g_perm[N_TOK];
__device__ int g_counts[NEXP];
__device__ int g_done;
__device__ int g_offsets[NEXP + 1];
__device__ int g_cursor[NEXP];
__device__ int g_ntiles;
__device__ int g_tile_e[MAXTILES];
__device__ int g_tile_start[MAXTILES];
// packed fp16 weights: [e][chunk16][t(0..3)][n(0..255)][w(0..1)]
// word(e,c,t,n,0) = (W[c*16+2t][n],   W[c*16+2t+1][n])
// word(e,c,t,n,1) = (W[c*16+2t+8][n], W[c*16+2t+9][n])
__device__ uint32_t g_W1p[NEXP * 8 * 4 * 512];
__device__ uint32_t g_W2p[NEXP * 16 * 4 * 512];

// ---------------- helpers ----------------
#define MMA_F16(acc, a, b) \
    asm volatile("mma.sync.aligned.m16n8k16.row.col.f32.f16.f16.f32 " \
        "{%0,%1,%2,%3}, {%4,%5,%6,%7}, {%8,%9}, {%0,%1,%2,%3};" \
        : "+f"((acc)[0]), "+f"((acc)[1]), "+f"((acc)[2]), "+f"((acc)[3]) \
        : "r"((a)[0]), "r"((a)[1]), "r"((a)[2]), "r"((a)[3]), \
          "r"((b)[0]), "r"((b)[1]))

#define CP_ASYNC16(dst, src) \
    asm volatile("cp.async.cg.shared.global [%0], [%1], 16;" :: "r"(dst), "l"(src))
#define CP_COMMIT() asm volatile("cp.async.commit_group;" ::: "memory")
#define CP_WAIT(n)  asm volatile("cp.async.wait_group %0;" :: "n"(n) : "memory")
#define BAR_PAIR(id) asm volatile("bar.sync %0, 64;" :: "r"(id) : "memory")

__device__ __forceinline__ uint32_t smem_u32(const void* p) {
    uint32_t a;
    asm("{ .reg .u64 t; cvta.to.shared.u64 t, %1; cvt.u32.u64 %0, t; }" : "=r"(a) : "l"(p));
    return a;
}
__device__ __forceinline__ uint32_t pack_h2(float lo, float hi) {
    __half2 h = __floats2half2_rn(lo, hi);
    return *(uint32_t*)&h;
}

// ---------------- pack weights into LDS.64 layout ----------------
__global__ __launch_bounds__(256) void pack_kernel(const float* __restrict__ W1,
                                                   const float* __restrict__ W2) {
    int i = blockIdx.x * 256 + threadIdx.x;
    {
        int e = i >> 15, r = i & 32767;
        int c = r >> 11, rr = r & 2047;
        int t = rr >> 9, q = rr & 511;
        int n = q >> 1,  w = q & 1;
        int k = c * 16 + 2 * t + 8 * w;
        const float* s = W2 + ((long)e * HID + k) * HID + n;
        g_W2p[i] = pack_h2(s[0], s[HID]);
    }
    if (i < NEXP * 16384) {
        int e = i >> 14, r = i & 16383;
        int c = r >> 11, rr = r & 2047;
        int t = rr >> 9, q = rr & 511;
        int n = q >> 1,  w = q & 1;
        int k = c * 16 + 2 * t + 8 * w;
        const float* s = W1 + ((long)e * DIM + k) * HID + n;
        g_W1p[i] = pack_h2(s[0], s[HID]);
    }
}

// ---------------- gate: fp32-exact argmax + last-block scan + tile table ----------------
#define GX_STR 132
__global__ __launch_bounds__(256) void gate_kernel(const float* __restrict__ x,
                                                   const float* __restrict__ Wg,
                                                   const float* __restrict__ bg) {
    extern __shared__ float sm[];
    float* xs  = sm;
    float* wgT = xs + 128 * GX_STR;
    float* bgs = wgT + 16 * GX_STR;
    __shared__ int hist[NEXP];
    __shared__ int tile_pre[NEXP];
    __shared__ int is_last;

    int tid = threadIdx.x;
    if (tid < NEXP) { hist[tid] = 0; bgs[tid] = bg[tid]; }
    for (int i = tid; i < DIM * NEXP; i += 256) {
        int k = i >> 4, e2 = i & 15;
        wgT[e2 * GX_STR + k] = Wg[i];
    }

    long base = (long)blockIdx.x * 128 * DIM;
    const float4* xg = (const float4*)(x + base);
    for (int i4 = tid; i4 < 128 * DIM / 4; i4 += 256) {
        float4 v = xg[i4];
        int row = i4 >> 5;
        int c4  = i4 & 31;
        *(float4*)(xs + row * GX_STR + c4 * 4) = v;
    }
    __syncthreads();

    int tcol = tid & 15;
    int trow = tid >> 4;

    float acc[8];
#pragma unroll
    for (int r = 0; r < 8; r++) acc[r] = bgs[tcol];
#pragma unroll 4
    for (int k = 0; k < DIM; k += 4) {
        float4 wv = *(const float4*)(wgT + tcol * GX_STR + k);
#pragma unroll
        for (int r = 0; r < 8; r++) {
            float4 xv = *(const float4*)(xs + (trow * 8 + r) * GX_STR + k);
            acc[r] = fmaf(xv.x, wv.x, acc[r]);
            acc[r] = fmaf(xv.y, wv.y, acc[r]);
            acc[r] = fmaf(xv.z, wv.z, acc[r]);
            acc[r] = fmaf(xv.w, wv.w, acc[r]);
        }
    }
#pragma unroll
    for (int r = 0; r < 8; r++) {
        float v = acc[r];
        int ei = tcol;
#pragma unroll
        for (int off = 8; off > 0; off >>= 1) {
            float ov = __shfl_xor_sync(0xffffffffu, v, off, 16);
            int   oe = __shfl_xor_sync(0xffffffffu, ei, off, 16);
            if (ov > v || (ov == v && oe < ei)) { v = ov; ei = oe; }
        }
        if (tcol == 0) {
            int t = blockIdx.x * 128 + trow * 8 + r;
            g_expert_idx[t] = ei;
            atomicAdd(&hist[ei], 1);
        }
    }
    __syncthreads();
    if (tid < NEXP && hist[tid]) atomicAdd(&g_counts[tid], hist[tid]);
    __threadfence();
    __syncthreads();
    if (tid == 0) {
        int d = atomicAdd(&g_done, 1);
        is_last = (d == NBLK - 1);
    }
    __syncthreads();
    if (is_last) {
        if (tid == 0) {
            int run = 0, trun = 0;
#pragma unroll
            for (int e = 0; e < NEXP; e++) {
                int c = g_counts[e];
                g_offsets[e] = run;
                g_cursor[e]  = run;
                tile_pre[e]  = trun;
                run  += c;
                trun += (c + 63) >> 6;
                g_counts[e] = 0;
            }
            g_offsets[NEXP] = run;
            g_ntiles = trun;
            g_done = 0;
        }
        __syncthreads();
        if (tid < NEXP) {
            int e = tid;
            int beg = g_offsets[e], cnt = g_offsets[e + 1] - beg;
            int nt = (cnt + 63) >> 6, tp = tile_pre[e];
            for (int i = 0; i < nt; i++) {
                g_tile_e[tp + i]     = e;
                g_tile_start[tp + i] = beg + 64 * i;
            }
        }
        __threadfence();
    }
}

__global__ __launch_bounds__(256) void scatter_kernel() {
    int t = blockIdx.x * 256 + threadIdx.x;
    int e = g_expert_idx[t];
    unsigned m  = __match_any_sync(0xffffffffu, e);
    int lane    = threadIdx.x & 31;
    int leader  = __ffs(m) - 1;
    int rank    = __popc(m & ((1u << lane) - 1));
    int base    = 0;
    if (lane == leader) base = atomicAdd(&g_cursor[e], __popc(m));
    base = __shfl_sync(0xffffffffu, base, leader);
    g_perm[base + rank] = t;
}

// ---------------- fp16 mma.sync grouped MLP: persistent, pairwise barriers ----------------
// 8 warps as 2(M) x 4(N); warp tile 32x64 (fm=2, fn=8); 12 chunks of k=32; 4 stages.
// cp ownership privatized: warp (wm,wn) copies rows [wm*4,wm*4+4) of slice wn
// (words [wn*128, wn*128+128) per row). Stage sync = bar.sync(1+wn, 64) between
// the two wm-partners only. Full __syncthreads only for gather / epilogue-1 / ps.
#define XS_STRW 68
#define H1_STRW 132
#define NCH 12
#define WROW 520
#define WS_STAGE (8 * WROW)
#define F_WS    0
#define F_B1S   (4 * WS_STAGE)
#define F_B2S   (F_B1S + 256)
#define F_W3S   (F_B2S + 256)
#define F_PS    (F_W3S + 256)
#define F_UNION (F_PS + 256)
#define MLP_SMEM ((F_UNION + 64 * H1_STRW) * 4)

// per-warp slice copy: 4 rows x 128 words (one cp group when followed by commit)
__device__ __forceinline__ void cp_slice(const uint32_t* __restrict__ chunk_base,
                                         uint32_t ws_stage_smem, int wm, int wn, int lane) {
#pragma unroll
    for (int i = 0; i < 4; i++) {
        int row = wm * 4 + i;
        uint32_t off = (uint32_t)(row * WROW + wn * 128 + lane * 4) * 4u;
        CP_ASYNC16(ws_stage_smem + off, chunk_base + (long)row * 512 + wn * 128 + lane * 4);
    }
}

__global__ __launch_bounds__(256, 2) void mlp_tc_kernel(
        const float* __restrict__ x,
        const float* __restrict__ b1, const float* __restrict__ b2,
        const float* __restrict__ W3, const float* __restrict__ b3,
        float* __restrict__ out) {
    extern __shared__ float sm[];
    float* b1s = sm + F_B1S;
    float* b2s = sm + F_B2S;
    float* w3s = sm + F_W3S;
    float* ps  = sm + F_PS;
    uint32_t* un = (uint32_t*)(sm + F_UNION);
    uint32_t ws0 = smem_u32(sm + F_WS);
    const uint32_t* wsw = (const uint32_t*)(sm + F_WS);

    int tid = threadIdx.x;
    int wid = tid >> 5, lid = tid & 31;
    int g = lid >> 2, t = lid & 3;
    int wm = wid & 1;
    int wn = wid >> 1;
    int bar_id = 1 + wn;

    int ntiles = g_ntiles;

    for (int tile = blockIdx.x; tile < ntiles; tile += MLP_GRID) {
        int e     = g_tile_e[tile];
        int start = g_tile_start[tile];
        int cnt   = min(64, g_offsets[e + 1] - start);

        b1s[tid] = b1[e * HID + tid];
        b2s[tid] = b2[e * HID + tid];
        w3s[tid] = W3[e * HID + tid];

        // gather A1 = x[perm] -> fp16 xs [64 rows][64 words, stride 68]
#pragma unroll
        for (int i = 0; i < 8; i++) {
            int f   = tid + 256 * i;
            int row = f >> 5;
            int c4  = f & 31;
            float4 v = make_float4(0.f, 0.f, 0.f, 0.f);
            if (row < cnt) {
                int gt = g_perm[start + row];
                v = *(const float4*)(x + (long)gt * DIM + c4 * 4);
            }
            uint32_t* dst = un + row * XS_STRW + c4 * 2;
            dst[0] = pack_h2(v.x, v.y);
            dst[1] = pack_h2(v.z, v.w);
        }

        const uint32_t* W1e = g_W1p + (long)e * 16384;
        const uint32_t* W2e = g_W2p + (long)e * 32768;

        float acc[2][8][4];
#pragma unroll
        for (int fm = 0; fm < 2; fm++)
#pragma unroll
            for (int fn = 0; fn < 8; fn++)
#pragma unroll
                for (int q = 0; q < 4; q++) acc[fm][fn][q] = 0.f;

        // prologue: each warp prefetches its slice for chunks 0,1,2
#pragma unroll
        for (int p = 0; p < 3; p++) {
            const uint32_t* src = (p < 4) ? (W1e + (long)p * 4096)
                                          : (W2e + (long)(p - 4) * 4096);
            cp_slice(src, ws0 + (uint32_t)((p & 3) * WS_STAGE) * 4u, wm, wn, lid);
            CP_COMMIT();
        }
        __syncthreads();                // xs + biases visible

#pragma unroll 1
        for (int ch = 0; ch < NCH; ch++) {
            if (ch < NCH - 2)       CP_WAIT(2);
            else if (ch == NCH - 2) CP_WAIT(1);
            else                    CP_WAIT(0);
            BAR_PAIR(bar_id);           // partner's slice half also landed
            if (ch + 3 < NCH) {
                int p = ch + 3;
                const uint32_t* src = (p < 4) ? (W1e + (long)p * 4096)
                                              : (W2e + (long)(p - 4) * 4096);
                cp_slice(src, ws0 + (uint32_t)((p & 3) * WS_STAGE) * 4u, wm, wn, lid);
                CP_COMMIT();
            }

            if (ch == 4) {
                __syncthreads();        // all warps done reading xs (chunks 0..3)
                // epilogue 1: h1 = fp16(relu(acc + b1)) into union (stride 132 words)
#pragma unroll
                for (int fm = 0; fm < 2; fm++) {
                    int r = wm * 32 + fm * 16 + g;
#pragma unroll
                    for (int fn = 0; fn < 8; fn++) {
                        int c = wn * 64 + fn * 8 + t * 2;
                        un[r * H1_STRW + c / 2] =
                            pack_h2(fmaxf(acc[fm][fn][0] + b1s[c],     0.f),
                                    fmaxf(acc[fm][fn][1] + b1s[c + 1], 0.f));
                        un[(r + 8) * H1_STRW + c / 2] =
                            pack_h2(fmaxf(acc[fm][fn][2] + b1s[c],     0.f),
                                    fmaxf(acc[fm][fn][3] + b1s[c + 1], 0.f));
                        acc[fm][fn][0] = 0.f; acc[fm][fn][1] = 0.f;
                        acc[fm][fn][2] = 0.f; acc[fm][fn][3] = 0.f;
                    }
                }
                __syncthreads();        // h1 visible to all warps
            }

            const uint32_t* stg = wsw + (ch & 3) * WS_STAGE;
#pragma unroll
            for (int kk = 0; kk < 2; kk++) {
                uint32_t a[2][4];
                if (ch < 4) {
#pragma unroll
                    for (int fm = 0; fm < 2; fm++) {
                        int row = wm * 32 + fm * 16 + g;
                        const uint32_t* xr = un + row * XS_STRW + ch * 16 + kk * 8 + t;
                        a[fm][0] = xr[0];
                        a[fm][1] = xr[8 * XS_STRW];
                        a[fm][2] = xr[4];
                        a[fm][3] = xr[8 * XS_STRW + 4];
                    }
                } else {
#pragma unroll
                    for (int fm = 0; fm < 2; fm++) {
                        int row = wm * 32 + fm * 16 + g;
                        const uint32_t* hr = un + row * H1_STRW + (ch - 4) * 16 + kk * 8 + t;
                        a[fm][0] = hr[0];
                        a[fm][1] = hr[8 * H1_STRW];
                        a[fm][2] = hr[4];
                        a[fm][3] = hr[8 * H1_STRW + 4];
                    }
                }
                uint32_t b[8][2];
                const uint2* wr = (const uint2*)(stg + (kk * 4 + t) * WROW + (wn * 64 + g) * 2);
#pragma unroll
                for (int fn = 0; fn < 8; fn++) {
                    uint2 bv = wr[fn * 8];
                    b[fn][0] = bv.x;
                    b[fn][1] = bv.y;
                }
#pragma unroll
                for (int fm = 0; fm < 2; fm++)
#pragma unroll
                    for (int fn = 0; fn < 8; fn++)
                        MMA_F16(acc[fm][fn], a[fm], b[fn]);
            }
        }

        // epilogue 2: y = relu(acc + b2) . w3 + b3
        float part[2][2];
#pragma unroll
        for (int fm = 0; fm < 2; fm++) { part[fm][0] = 0.f; part[fm][1] = 0.f; }
#pragma unroll
        for (int fm = 0; fm < 2; fm++)
#pragma unroll
            for (int fn = 0; fn < 8; fn++) {
                int c = wn * 64 + fn * 8 + t * 2;
                part[fm][0] = fmaf(fmaxf(acc[fm][fn][0] + b2s[c],     0.f), w3s[c],     part[fm][0]);
                part[fm][0] = fmaf(fmaxf(acc[fm][fn][1] + b2s[c + 1], 0.f), w3s[c + 1], part[fm][0]);
                part[fm][1] = fmaf(fmaxf(acc[fm][fn][2] + b2s[c],     0.f), w3s[c],     part[fm][1]);
                part[fm][1] = fmaf(fmaxf(acc[fm][fn][3] + b2s[c + 1], 0.f), w3s[c + 1], part[fm][1]);
            }
#pragma unroll
        for (int fm = 0; fm < 2; fm++)
#pragma unroll
            for (int h = 0; h < 2; h++) {
                part[fm][h] += __shfl_xor_sync(0xffffffffu, part[fm][h], 1);
                part[fm][h] += __shfl_xor_sync(0xffffffffu, part[fm][h], 2);
            }
        if (t == 0) {
#pragma unroll
            for (int fm = 0; fm < 2; fm++) {
                int r = wm * 32 + fm * 16 + g;
                ps[r * 4 + wn]       = part[fm][0];
                ps[(r + 8) * 4 + wn] = part[fm][1];
            }
        }
        __syncthreads();

        if (tid < cnt)
            out[g_perm[start + tid]] = ps[tid * 4] + ps[tid * 4 + 1]
                                     + ps[tid * 4 + 2] + ps[tid * 4 + 3] + b3[e];
        __syncthreads();                // ps/un safe to reuse next tile
    }
}

// ---------------- launch ----------------
extern "C" void kernel_launch(void* const* d_in, const int* in_sizes, int n_in,
                              void* d_out, int out_size) {
    const float* x  = (const float*)d_in[0];
    const float* Wg = (const float*)d_in[1];
    const float* bg = (const float*)d_in[2];
    const float* W1 = (const float*)d_in[3];
    const float* b1 = (const float*)d_in[4];
    const float* W2 = (const float*)d_in[5];
    const float* b2 = (const float*)d_in[6];
    const float* W3 = (const float*)d_in[7];
    const float* b3 = (const float*)d_in[8];
    float* out = (float*)d_out;

    size_t gate_smem = (size_t)(128 * GX_STR + 16 * GX_STR + 16) * sizeof(float);
    cudaFuncSetAttribute(gate_kernel, cudaFuncAttributeMaxDynamicSharedMemorySize, (int)gate_smem);
    cudaFuncSetAttribute(mlp_tc_kernel, cudaFuncAttributeMaxDynamicSharedMemorySize, MLP_SMEM);

    pack_kernel<<<NEXP * 32768 / 256, 256>>>(W1, W2);
    gate_kernel<<<NBLK, 256, gate_smem>>>(x, Wg, bg);
    scatter_kernel<<<N_TOK / 256, 256>>>();
    mlp_tc_kernel<<<MLP_GRID, 256, MLP_SMEM>>>(x, b1, b2, W3, b3, out);
    (void)n_in; (void)in_sizes; (void)out_size;
}

// round 10
// speedup vs baseline: 6.8116x; 1.1000x over previous
#include <cuda_runtime.h>
#include <cuda_fp16.h>
#include <cstdint>

#define N_TOK 65536
#define DIM   128
#define HID   256
#define NEXP  16
#define NBLK  (N_TOK / 128)
#define MAXTILES 1040
#define MLP_GRID 296

// ---------------- device scratch ----------------
__device__ int g_expert_idx[N_TOK];          // (kept for debug; not read by mlp)
__device__ int g_perm_e[NEXP][N_TOK];        // per-expert token lists (4 MB)
__device__ int g_counts[NEXP];               // running bases (zeroed by last block each run)
__device__ int g_done;
__device__ int g_ecnt[NEXP];                 // final per-expert counts snapshot
__device__ int g_ntiles;
__device__ int g_tile_e[MAXTILES];
__device__ int g_tile_ls[MAXTILES];          // local start within expert list
// packed fp16 weights: [e][chunk16][t(0..3)][n(0..255)][w(0..1)]
// word(e,c,t,n,0) = (W[c*16+2t][n],   W[c*16+2t+1][n])
// word(e,c,t,n,1) = (W[c*16+2t+8][n], W[c*16+2t+9][n])
__device__ uint32_t g_W1p[NEXP * 8 * 4 * 512];
__device__ uint32_t g_W2p[NEXP * 16 * 4 * 512];

// ---------------- helpers ----------------
#define MMA_F16(acc, a, b) \
    asm volatile("mma.sync.aligned.m16n8k16.row.col.f32.f16.f16.f32 " \
        "{%0,%1,%2,%3}, {%4,%5,%6,%7}, {%8,%9}, {%0,%1,%2,%3};" \
        : "+f"((acc)[0]), "+f"((acc)[1]), "+f"((acc)[2]), "+f"((acc)[3]) \
        : "r"((a)[0]), "r"((a)[1]), "r"((a)[2]), "r"((a)[3]), \
          "r"((b)[0]), "r"((b)[1]))

#define CP_ASYNC16(dst, src) \
    asm volatile("cp.async.cg.shared.global [%0], [%1], 16;" :: "r"(dst), "l"(src))
#define CP_COMMIT() asm volatile("cp.async.commit_group;" ::: "memory")
#define CP_WAIT(n)  asm volatile("cp.async.wait_group %0;" :: "n"(n) : "memory")
#define BAR_PAIR(id) asm volatile("bar.sync %0, 64;" :: "r"(id) : "memory")

__device__ __forceinline__ uint32_t smem_u32(const void* p) {
    uint32_t a;
    asm("{ .reg .u64 t; cvta.to.shared.u64 t, %1; cvt.u32.u64 %0, t; }" : "=r"(a) : "l"(p));
    return a;
}
__device__ __forceinline__ uint32_t pack_h2(float lo, float hi) {
    __half2 h = __floats2half2_rn(lo, hi);
    return *(uint32_t*)&h;
}

// ---------------- fused prep: pack weights + gate + scatter + tile table ----------------
#define GX_STR 132
__global__ __launch_bounds__(256) void prep_kernel(const float* __restrict__ x,
                                                   const float* __restrict__ Wg,
                                                   const float* __restrict__ bg,
                                                   const float* __restrict__ W1,
                                                   const float* __restrict__ W2) {
    extern __shared__ float sm[];
    float* xs  = sm;                         // 128 x 132
    float* wgT = xs + 128 * GX_STR;          // 16 x 132
    float* bgs = wgT + 16 * GX_STR;          // 16
    __shared__ int hist[NEXP];
    __shared__ int sh_base[NEXP];
    __shared__ int tile_pre[NEXP];
    __shared__ int is_last;

    int tid = threadIdx.x;
    int blk = blockIdx.x;
    if (tid < NEXP) { hist[tid] = 0; bgs[tid] = bg[tid]; }
    for (int i = tid; i < DIM * NEXP; i += 256) {
        int k = i >> 4, e2 = i & 15;
        wgT[e2 * GX_STR + k] = Wg[i];
    }

    long base = (long)blk * 128 * DIM;
    const float4* xg = (const float4*)(x + base);
    for (int i4 = tid; i4 < 128 * DIM / 4; i4 += 256) {
        float4 v = xg[i4];
        int row = i4 >> 5;
        int c4  = i4 & 31;
        *(float4*)(xs + row * GX_STR + c4 * 4) = v;
    }

    // ---- pack slice: this block packs 1024 W2 words + 512 W1 words ----
    // (independent of gate work; overlaps with the smem staging above)
#pragma unroll
    for (int j = 0; j < 4; j++) {
        int i = blk * 1024 + j * 256 + tid;          // 0 .. NEXP*32768-1
        int e = i >> 15, r = i & 32767;
        int c = r >> 11, rr = r & 2047;
        int t = rr >> 9, q = rr & 511;
        int n = q >> 1,  w = q & 1;
        int k = c * 16 + 2 * t + 8 * w;
        const float* s = W2 + ((long)e * HID + k) * HID + n;
        g_W2p[i] = pack_h2(s[0], s[HID]);
    }
#pragma unroll
    for (int j = 0; j < 2; j++) {
        int i = blk * 512 + j * 256 + tid;           // 0 .. NEXP*16384-1
        int e = i >> 14, r = i & 16383;
        int c = r >> 11, rr = r & 2047;
        int t = rr >> 9, q = rr & 511;
        int n = q >> 1,  w = q & 1;
        int k = c * 16 + 2 * t + 8 * w;
        const float* s = W1 + ((long)e * DIM + k) * HID + n;
        g_W1p[i] = pack_h2(s[0], s[HID]);
    }

    __syncthreads();

    int tcol = tid & 15;
    int trow = tid >> 4;

    float acc[8];
#pragma unroll
    for (int r = 0; r < 8; r++) acc[r] = bgs[tcol];
#pragma unroll 4
    for (int k = 0; k < DIM; k += 4) {
        float4 wv = *(const float4*)(wgT + tcol * GX_STR + k);
#pragma unroll
        for (int r = 0; r < 8; r++) {
            float4 xv = *(const float4*)(xs + (trow * 8 + r) * GX_STR + k);
            acc[r] = fmaf(xv.x, wv.x, acc[r]);
            acc[r] = fmaf(xv.y, wv.y, acc[r]);
            acc[r] = fmaf(xv.z, wv.z, acc[r]);
            acc[r] = fmaf(xv.w, wv.w, acc[r]);
        }
    }

    int ei_r[8], rank_r[8];
#pragma unroll
    for (int r = 0; r < 8; r++) {
        float v = acc[r];
        int ei = tcol;
#pragma unroll
        for (int off = 8; off > 0; off >>= 1) {
            float ov = __shfl_xor_sync(0xffffffffu, v, off, 16);
            int   oe = __shfl_xor_sync(0xffffffffu, ei, off, 16);
            if (ov > v || (ov == v && oe < ei)) { v = ov; ei = oe; }
        }
        ei_r[r] = ei;
        rank_r[r] = -1;
        if (tcol == 0) {
            rank_r[r] = atomicAdd(&hist[ei], 1);     // rank within block for expert ei
        }
    }
    __syncthreads();
    // claim per-expert base ranges for this block
    if (tid < NEXP) sh_base[tid] = hist[tid] ? atomicAdd(&g_counts[tid], hist[tid]) : 0;
    __syncthreads();
    // write tokens into per-expert lists
#pragma unroll
    for (int r = 0; r < 8; r++) {
        if (tcol == 0) {
            int token = blk * 128 + trow * 8 + r;
            g_perm_e[ei_r[r]][sh_base[ei_r[r]] + rank_r[r]] = token;
        }
    }
    __threadfence();
    __syncthreads();
    if (tid == 0) {
        int d = atomicAdd(&g_done, 1);
        is_last = (d == NBLK - 1);
    }
    __syncthreads();
    if (is_last) {
        if (tid == 0) {
            int trun = 0;
#pragma unroll
            for (int e = 0; e < NEXP; e++) {
                int c = g_counts[e];
                g_ecnt[e]   = c;
                tile_pre[e] = trun;
                trun += (c + 63) >> 6;
                g_counts[e] = 0;                     // reset for next replay
            }
            g_ntiles = trun;
            g_done = 0;
        }
        __syncthreads();
        if (tid < NEXP) {
            int e = tid;
            int cnt = g_ecnt[e];
            int nt = (cnt + 63) >> 6, tp = tile_pre[e];
            for (int i = 0; i < nt; i++) {
                g_tile_e[tp + i]  = e;
                g_tile_ls[tp + i] = 64 * i;
            }
        }
        __threadfence();
    }
}

// ---------------- fp16 mma.sync grouped MLP: persistent, pairwise barriers ----------------
// 8 warps as 2(M) x 4(N); warp tile 32x64 (fm=2, fn=8); 12 chunks of k=32; 4 stages.
#define XS_STRW 68
#define H1_STRW 132
#define NCH 12
#define WROW 520
#define WS_STAGE (8 * WROW)
#define F_WS    0
#define F_B1S   (4 * WS_STAGE)
#define F_B2S   (F_B1S + 256)
#define F_W3S   (F_B2S + 256)
#define F_PS    (F_W3S + 256)
#define F_UNION (F_PS + 256)
#define MLP_SMEM ((F_UNION + 64 * H1_STRW) * 4)

__device__ __forceinline__ void cp_slice(const uint32_t* __restrict__ chunk_base,
                                         uint32_t ws_stage_smem, int wm, int wn, int lane) {
#pragma unroll
    for (int i = 0; i < 4; i++) {
        int row = wm * 4 + i;
        uint32_t off = (uint32_t)(row * WROW + wn * 128 + lane * 4) * 4u;
        CP_ASYNC16(ws_stage_smem + off, chunk_base + (long)row * 512 + wn * 128 + lane * 4);
    }
}

__global__ __launch_bounds__(256, 2) void mlp_tc_kernel(
        const float* __restrict__ x,
        const float* __restrict__ b1, const float* __restrict__ b2,
        const float* __restrict__ W3, const float* __restrict__ b3,
        float* __restrict__ out) {
    extern __shared__ float sm[];
    float* b1s = sm + F_B1S;
    float* b2s = sm + F_B2S;
    float* w3s = sm + F_W3S;
    float* ps  = sm + F_PS;
    uint32_t* un = (uint32_t*)(sm + F_UNION);
    uint32_t ws0 = smem_u32(sm + F_WS);
    const uint32_t* wsw = (const uint32_t*)(sm + F_WS);

    int tid = threadIdx.x;
    int wid = tid >> 5, lid = tid & 31;
    int g = lid >> 2, t = lid & 3;
    int wm = wid & 1;
    int wn = wid >> 1;
    int bar_id = 1 + wn;

    int ntiles = g_ntiles;

    for (int tile = blockIdx.x; tile < ntiles; tile += MLP_GRID) {
        int e   = g_tile_e[tile];
        int ls  = g_tile_ls[tile];
        int cnt = min(64, g_ecnt[e] - ls);
        const int* perm = g_perm_e[e] + ls;

        b1s[tid] = b1[e * HID + tid];
        b2s[tid] = b2[e * HID + tid];
        w3s[tid] = W3[e * HID + tid];

        // gather A1 = x[perm] -> fp16 xs [64 rows][64 words, stride 68]
#pragma unroll
        for (int i = 0; i < 8; i++) {
            int f   = tid + 256 * i;
            int row = f >> 5;
            int c4  = f & 31;
            float4 v = make_float4(0.f, 0.f, 0.f, 0.f);
            if (row < cnt) {
                int gt = perm[row];
                v = *(const float4*)(x + (long)gt * DIM + c4 * 4);
            }
            uint32_t* dst = un + row * XS_STRW + c4 * 2;
            dst[0] = pack_h2(v.x, v.y);
            dst[1] = pack_h2(v.z, v.w);
        }

        const uint32_t* W1e = g_W1p + (long)e * 16384;
        const uint32_t* W2e = g_W2p + (long)e * 32768;

        float acc[2][8][4];
#pragma unroll
        for (int fm = 0; fm < 2; fm++)
#pragma unroll
            for (int fn = 0; fn < 8; fn++)
#pragma unroll
                for (int q = 0; q < 4; q++) acc[fm][fn][q] = 0.f;

        // prologue: each warp prefetches its slice for chunks 0,1,2
#pragma unroll
        for (int p = 0; p < 3; p++) {
            const uint32_t* src = (p < 4) ? (W1e + (long)p * 4096)
                                          : (W2e + (long)(p - 4) * 4096);
            cp_slice(src, ws0 + (uint32_t)((p & 3) * WS_STAGE) * 4u, wm, wn, lid);
            CP_COMMIT();
        }
        __syncthreads();                // xs + biases visible

#pragma unroll 1
        for (int ch = 0; ch < NCH; ch++) {
            if (ch < NCH - 2)       CP_WAIT(2);
            else if (ch == NCH - 2) CP_WAIT(1);
            else                    CP_WAIT(0);
            BAR_PAIR(bar_id);
            if (ch + 3 < NCH) {
                int p = ch + 3;
                const uint32_t* src = (p < 4) ? (W1e + (long)p * 4096)
                                              : (W2e + (long)(p - 4) * 4096);
                cp_slice(src, ws0 + (uint32_t)((p & 3) * WS_STAGE) * 4u, wm, wn, lid);
                CP_COMMIT();
            }

            if (ch == 4) {
                __syncthreads();        // all warps done reading xs (chunks 0..3)
                // epilogue 1: h1 = fp16(relu(acc + b1)) into union (stride 132 words)
#pragma unroll
                for (int fm = 0; fm < 2; fm++) {
                    int r = wm * 32 + fm * 16 + g;
#pragma unroll
                    for (int fn = 0; fn < 8; fn++) {
                        int c = wn * 64 + fn * 8 + t * 2;
                        un[r * H1_STRW + c / 2] =
                            pack_h2(fmaxf(acc[fm][fn][0] + b1s[c],     0.f),
                                    fmaxf(acc[fm][fn][1] + b1s[c + 1], 0.f));
                        un[(r + 8) * H1_STRW + c / 2] =
                            pack_h2(fmaxf(acc[fm][fn][2] + b1s[c],     0.f),
                                    fmaxf(acc[fm][fn][3] + b1s[c + 1], 0.f));
                        acc[fm][fn][0] = 0.f; acc[fm][fn][1] = 0.f;
                        acc[fm][fn][2] = 0.f; acc[fm][fn][3] = 0.f;
                    }
                }
                __syncthreads();        // h1 visible to all warps
            }

            const uint32_t* stg = wsw + (ch & 3) * WS_STAGE;
#pragma unroll
            for (int kk = 0; kk < 2; kk++) {
                uint32_t a[2][4];
                if (ch < 4) {
#pragma unroll
                    for (int fm = 0; fm < 2; fm++) {
                        int row = wm * 32 + fm * 16 + g;
                        const uint32_t* xr = un + row * XS_STRW + ch * 16 + kk * 8 + t;
                        a[fm][0] = xr[0];
                        a[fm][1] = xr[8 * XS_STRW];
                        a[fm][2] = xr[4];
                        a[fm][3] = xr[8 * XS_STRW + 4];
                    }
                } else {
#pragma unroll
                    for (int fm = 0; fm < 2; fm++) {
                        int row = wm * 32 + fm * 16 + g;
                        const uint32_t* hr = un + row * H1_STRW + (ch - 4) * 16 + kk * 8 + t;
                        a[fm][0] = hr[0];
                        a[fm][1] = hr[8 * H1_STRW];
                        a[fm][2] = hr[4];
                        a[fm][3] = hr[8 * H1_STRW + 4];
                    }
                }
                uint32_t b[8][2];
                const uint2* wr = (const uint2*)(stg + (kk * 4 + t) * WROW + (wn * 64 + g) * 2);
#pragma unroll
                for (int fn = 0; fn < 8; fn++) {
                    uint2 bv = wr[fn * 8];
                    b[fn][0] = bv.x;
                    b[fn][1] = bv.y;
                }
#pragma unroll
                for (int fm = 0; fm < 2; fm++)
#pragma unroll
                    for (int fn = 0; fn < 8; fn++)
                        MMA_F16(acc[fm][fn], a[fm], b[fn]);
            }
        }

        // epilogue 2: y = relu(acc + b2) . w3 + b3
        float part[2][2];
#pragma unroll
        for (int fm = 0; fm < 2; fm++) { part[fm][0] = 0.f; part[fm][1] = 0.f; }
#pragma unroll
        for (int fm = 0; fm < 2; fm++)
#pragma unroll
            for (int fn = 0; fn < 8; fn++) {
                int c = wn * 64 + fn * 8 + t * 2;
                part[fm][0] = fmaf(fmaxf(acc[fm][fn][0] + b2s[c],     0.f), w3s[c],     part[fm][0]);
                part[fm][0] = fmaf(fmaxf(acc[fm][fn][1] + b2s[c + 1], 0.f), w3s[c + 1], part[fm][0]);
                part[fm][1] = fmaf(fmaxf(acc[fm][fn][2] + b2s[c],     0.f), w3s[c],     part[fm][1]);
                part[fm][1] = fmaf(fmaxf(acc[fm][fn][3] + b2s[c + 1], 0.f), w3s[c + 1], part[fm][1]);
            }
#pragma unroll
        for (int fm = 0; fm < 2; fm++)
#pragma unroll
            for (int h = 0; h < 2; h++) {
                part[fm][h] += __shfl_xor_sync(0xffffffffu, part[fm][h], 1);
                part[fm][h] += __shfl_xor_sync(0xffffffffu, part[fm][h], 2);
            }
        if (t == 0) {
#pragma unroll
            for (int fm = 0; fm < 2; fm++) {
                int r = wm * 32 + fm * 16 + g;
                ps[r * 4 + wn]       = part[fm][0];
                ps[(r + 8) * 4 + wn] = part[fm][1];
            }
        }
        __syncthreads();

        if (tid < cnt)
            out[perm[tid]] = ps[tid * 4] + ps[tid * 4 + 1]
                           + ps[tid * 4 + 2] + ps[tid * 4 + 3] + b3[e];
        __syncthreads();                // ps/un safe to reuse next tile
    }
}

// ---------------- launch ----------------
extern "C" void kernel_launch(void* const* d_in, const int* in_sizes, int n_in,
                              void* d_out, int out_size) {
    const float* x  = (const float*)d_in[0];
    const float* Wg = (const float*)d_in[1];
    const float* bg = (const float*)d_in[2];
    const float* W1 = (const float*)d_in[3];
    const float* b1 = (const float*)d_in[4];
    const float* W2 = (const float*)d_in[5];
    const float* b2 = (const float*)d_in[6];
    const float* W3 = (const float*)d_in[7];
    const float* b3 = (const float*)d_in[8];
    float* out = (float*)d_out;

    size_t prep_smem = (size_t)(128 * GX_STR + 16 * GX_STR + 16) * sizeof(float);
    cudaFuncSetAttribute(prep_kernel, cudaFuncAttributeMaxDynamicSharedMemorySize, (int)prep_smem);
    cudaFuncSetAttribute(mlp_tc_kernel, cudaFuncAttributeMaxDynamicSharedMemorySize, MLP_SMEM);

    prep_kernel<<<NBLK, 256, prep_smem>>>(x, Wg, bg, W1, W2);
    mlp_tc_kernel<<<MLP_GRID, 256, MLP_SMEM>>>(x, b1, b2, W3, b3, out);
    (void)n_in; (void)in_sizes; (void)out_size;
}